// round 2
// baseline (speedup 1.0000x reference)
#include <cuda_runtime.h>
#include <math.h>
#include <stdint.h>

// Problem constants (AttentionBlock_32031866094255)
constexpr int kB  = 8;
constexpr int kNQ = 4096;
constexpr int kNS = 4096;
constexpr int kC  = 2048;
constexpr int kD  = 512;
constexpr int kMQ = kB * kNQ;   // 32768
constexpr int kMK = kB * kNS;   // 32768

// Scratch (allocation-free rule: __device__ globals)
__device__ float g_qp[(size_t)kMQ * kC];   // 268 MB
__device__ float g_kp[(size_t)kMK * kC];   // 268 MB
__device__ float g_rowsum[kMQ];

// ---------------------------------------------------------------------------
// Block-wide deterministic sum reduction (fixed tree -> deterministic).
// ---------------------------------------------------------------------------
__device__ __forceinline__ float block_reduce_sum(float v) {
    __shared__ float red[32];
    __shared__ float total;
    #pragma unroll
    for (int o = 16; o > 0; o >>= 1) v += __shfl_down_sync(0xffffffffu, v, o);
    const int lane = threadIdx.x & 31;
    const int w = threadIdx.x >> 5;
    if (lane == 0) red[w] = v;
    __syncthreads();
    if (w == 0) {
        v = (lane < (int)(blockDim.x >> 5)) ? red[lane] : 0.0f;
        #pragma unroll
        for (int o = 16; o > 0; o >>= 1) v += __shfl_down_sync(0xffffffffu, v, o);
        if (lane == 0) total = v;
    }
    __syncthreads();
    return total;
}

// ---------------------------------------------------------------------------
// Projection GEMM: Y[m,n] = sum_c X[m,c] * W[n,c] + bias[n]
// X: [M, kC] row-major, W: [kC, kC] row-major (both K-major -> A*B^T form)
// Tile 128x128, BK=16, 256 threads, 8x8 per thread.
// ---------------------------------------------------------------------------
__global__ __launch_bounds__(256, 2)
void proj_gemm(const float* __restrict__ X, const float* __restrict__ W,
               const float* __restrict__ bias, float* __restrict__ Y) {
    __shared__ float As[16][128];
    __shared__ float Bs[16][128];
    const int m0 = blockIdx.y * 128;
    const int n0 = blockIdx.x * 128;
    const int tid = threadIdx.x;
    const int tx = tid & 15;
    const int ty = tid >> 4;
    float acc[8][8] = {};
    for (int k0 = 0; k0 < kC; k0 += 16) {
        #pragma unroll
        for (int it = 0; it < 2; ++it) {
            const int idx = tid + it * 256;
            const int r  = idx >> 2;
            const int c4 = (idx & 3) * 4;
            float4 a = *(const float4*)(X + (size_t)(m0 + r) * kC + k0 + c4);
            As[c4 + 0][r] = a.x; As[c4 + 1][r] = a.y;
            As[c4 + 2][r] = a.z; As[c4 + 3][r] = a.w;
            float4 b = *(const float4*)(W + (size_t)(n0 + r) * kC + k0 + c4);
            Bs[c4 + 0][r] = b.x; Bs[c4 + 1][r] = b.y;
            Bs[c4 + 2][r] = b.z; Bs[c4 + 3][r] = b.w;
        }
        __syncthreads();
        #pragma unroll
        for (int k = 0; k < 16; ++k) {
            float a[8], b[8];
            *(float4*)&a[0] = *(const float4*)&As[k][ty * 8];
            *(float4*)&a[4] = *(const float4*)&As[k][ty * 8 + 4];
            *(float4*)&b[0] = *(const float4*)&Bs[k][tx * 8];
            *(float4*)&b[4] = *(const float4*)&Bs[k][tx * 8 + 4];
            #pragma unroll
            for (int i = 0; i < 8; ++i)
                #pragma unroll
                for (int j = 0; j < 8; ++j)
                    acc[i][j] = fmaf(a[i], b[j], acc[i][j]);
        }
        __syncthreads();
    }
    #pragma unroll
    for (int i = 0; i < 8; ++i) {
        const int m = m0 + ty * 8 + i;
        #pragma unroll
        for (int j = 0; j < 8; j += 4) {
            const int n = n0 + tx * 8 + j;
            float4 o;
            o.x = acc[i][j + 0] + bias[n + 0];
            o.y = acc[i][j + 1] + bias[n + 1];
            o.z = acc[i][j + 2] + bias[n + 2];
            o.w = acc[i][j + 3] + bias[n + 3];
            *(float4*)(Y + (size_t)m * kC + n) = o;
        }
    }
}

// ---------------------------------------------------------------------------
// In-place row l2norm over rows of length kC (matches ref: x / max(||x||, 1e-12))
// ---------------------------------------------------------------------------
__global__ void l2norm_rows(float* __restrict__ y) {
    float* p = y + (size_t)blockIdx.x * kC;
    float ss = 0.0f;
    #pragma unroll
    for (int i = threadIdx.x * 4; i < kC; i += 1024) {
        float4 v = *(const float4*)(p + i);
        ss += v.x * v.x + v.y * v.y + v.z * v.z + v.w * v.w;
    }
    const float tot = block_reduce_sum(ss);
    const float inv = 1.0f / fmaxf(sqrtf(tot), 1e-12f);
    #pragma unroll
    for (int i = threadIdx.x * 4; i < kC; i += 1024) {
        float4 v = *(const float4*)(p + i);
        v.x *= inv; v.y *= inv; v.z *= inv; v.w *= inv;
        *(float4*)(p + i) = v;
    }
}

// ---------------------------------------------------------------------------
// QK^T + fixed-max exp: P[b,q,s] = exp(scale*(qp.kp) - scale - 1000*mask[b,s])
// (cos <= 1 => max logit <= scale, so fixed max is exact; masked entries
//  underflow to 0.0f exactly as in the fp32 reference softmax.)
// Writes unnormalized P directly into the attn output region.
// ---------------------------------------------------------------------------
__global__ __launch_bounds__(256, 2)
void attn_p(const float* __restrict__ qp, const float* __restrict__ kp,
            const float* __restrict__ mask, const float* __restrict__ scale_ptr,
            float* __restrict__ P) {
    __shared__ float As[16][128];
    __shared__ float Bs[16][128];
    const int b = blockIdx.z;
    const float* A  = qp + (size_t)b * kNQ * kC;
    const float* Bm = kp + (size_t)b * kNS * kC;
    const int m0 = blockIdx.y * 128;
    const int n0 = blockIdx.x * 128;
    const int tid = threadIdx.x;
    const int tx = tid & 15;
    const int ty = tid >> 4;
    float acc[8][8] = {};
    for (int k0 = 0; k0 < kC; k0 += 16) {
        #pragma unroll
        for (int it = 0; it < 2; ++it) {
            const int idx = tid + it * 256;
            const int r  = idx >> 2;
            const int c4 = (idx & 3) * 4;
            float4 a = *(const float4*)(A + (size_t)(m0 + r) * kC + k0 + c4);
            As[c4 + 0][r] = a.x; As[c4 + 1][r] = a.y;
            As[c4 + 2][r] = a.z; As[c4 + 3][r] = a.w;
            float4 bb = *(const float4*)(Bm + (size_t)(n0 + r) * kC + k0 + c4);
            Bs[c4 + 0][r] = bb.x; Bs[c4 + 1][r] = bb.y;
            Bs[c4 + 2][r] = bb.z; Bs[c4 + 3][r] = bb.w;
        }
        __syncthreads();
        #pragma unroll
        for (int k = 0; k < 16; ++k) {
            float a[8], b[8];
            *(float4*)&a[0] = *(const float4*)&As[k][ty * 8];
            *(float4*)&a[4] = *(const float4*)&As[k][ty * 8 + 4];
            *(float4*)&b[0] = *(const float4*)&Bs[k][tx * 8];
            *(float4*)&b[4] = *(const float4*)&Bs[k][tx * 8 + 4];
            #pragma unroll
            for (int i = 0; i < 8; ++i)
                #pragma unroll
                for (int j = 0; j < 8; ++j)
                    acc[i][j] = fmaf(a[i], b[j], acc[i][j]);
        }
        __syncthreads();
    }
    const float sc = scale_ptr[0];
    float mk[8];
    #pragma unroll
    for (int j = 0; j < 8; ++j)
        mk[j] = mask[(size_t)b * kNS + n0 + tx * 8 + j];
    #pragma unroll
    for (int i = 0; i < 8; ++i) {
        const int m = m0 + ty * 8 + i;
        float* prow = P + ((size_t)b * kNQ + m) * kNS + n0 + tx * 8;
        #pragma unroll
        for (int j = 0; j < 8; j += 4) {
            float4 o;
            o.x = expf(sc * acc[i][j + 0] - sc - 1000.0f * mk[j + 0]);
            o.y = expf(sc * acc[i][j + 1] - sc - 1000.0f * mk[j + 1]);
            o.z = expf(sc * acc[i][j + 2] - sc - 1000.0f * mk[j + 2]);
            o.w = expf(sc * acc[i][j + 3] - sc - 1000.0f * mk[j + 3]);
            *(float4*)(prow + j) = o;
        }
    }
}

// ---------------------------------------------------------------------------
// Deterministic row sums of unnormalized P (one block per (b,q) row).
// ---------------------------------------------------------------------------
__global__ void row_sum(const float* __restrict__ P, float* __restrict__ rs) {
    const float* p = P + (size_t)blockIdx.x * kNS;
    float s = 0.0f;
    #pragma unroll
    for (int i = threadIdx.x * 4; i < kNS; i += 1024) {
        float4 v = *(const float4*)(p + i);
        s += v.x + v.y + v.z + v.w;
    }
    const float tot = block_reduce_sum(s);
    if (threadIdx.x == 0) rs[blockIdx.x] = tot;
}

// ---------------------------------------------------------------------------
// out[b,q,d] = att_wt * (sum_s P[b,q,s] * v[b,s,d]) / rowsum[b,q] + org_wt*idt
// A = P (K-major), B = v (N-major). Tile 128x128, BK=16.
// ---------------------------------------------------------------------------
__global__ __launch_bounds__(256, 2)
void out_gemm(const float* __restrict__ P, const float* __restrict__ V,
              const float* __restrict__ idt, const float* __restrict__ rs,
              const float* __restrict__ attwt, const float* __restrict__ orgwt,
              float* __restrict__ out) {
    __shared__ float As[16][128];
    __shared__ float Bs[16][128];
    const int b = blockIdx.z;
    const float* A  = P + (size_t)b * kNQ * kNS;
    const float* Bv = V + (size_t)b * kNS * kD;
    const int m0 = blockIdx.y * 128;
    const int n0 = blockIdx.x * 128;
    const int tid = threadIdx.x;
    const int tx = tid & 15;
    const int ty = tid >> 4;
    float acc[8][8] = {};
    for (int k0 = 0; k0 < kNS; k0 += 16) {
        #pragma unroll
        for (int it = 0; it < 2; ++it) {
            const int idx = tid + it * 256;
            const int r  = idx >> 2;
            const int c4 = (idx & 3) * 4;
            float4 a = *(const float4*)(A + (size_t)(m0 + r) * kNS + k0 + c4);
            As[c4 + 0][r] = a.x; As[c4 + 1][r] = a.y;
            As[c4 + 2][r] = a.z; As[c4 + 3][r] = a.w;
            const int br = idx >> 5;          // 16 rows
            const int bc = (idx & 31) * 4;    // 128 cols
            float4 v = *(const float4*)(Bv + (size_t)(k0 + br) * kD + n0 + bc);
            *(float4*)&Bs[br][bc] = v;
        }
        __syncthreads();
        #pragma unroll
        for (int k = 0; k < 16; ++k) {
            float a[8], b[8];
            *(float4*)&a[0] = *(const float4*)&As[k][ty * 8];
            *(float4*)&a[4] = *(const float4*)&As[k][ty * 8 + 4];
            *(float4*)&b[0] = *(const float4*)&Bs[k][tx * 8];
            *(float4*)&b[4] = *(const float4*)&Bs[k][tx * 8 + 4];
            #pragma unroll
            for (int i = 0; i < 8; ++i)
                #pragma unroll
                for (int j = 0; j < 8; ++j)
                    acc[i][j] = fmaf(a[i], b[j], acc[i][j]);
        }
        __syncthreads();
    }
    const float aw = attwt[0];
    const float ow = orgwt[0];
    #pragma unroll
    for (int i = 0; i < 8; ++i) {
        const int m = m0 + ty * 8 + i;
        const float inv = 1.0f / rs[(size_t)b * kNQ + m];
        const float* irow = idt + ((size_t)b * kNQ + m) * kD + n0 + tx * 8;
        float* orow = out + ((size_t)b * kNQ + m) * kD + n0 + tx * 8;
        #pragma unroll
        for (int j = 0; j < 8; j += 4) {
            float4 id4 = *(const float4*)(irow + j);
            float4 o;
            o.x = aw * acc[i][j + 0] * inv + ow * id4.x;
            o.y = aw * acc[i][j + 1] * inv + ow * id4.y;
            o.z = aw * acc[i][j + 2] * inv + ow * id4.z;
            o.w = aw * acc[i][j + 3] * inv + ow * id4.w;
            *(float4*)(orow + j) = o;
        }
    }
}

// ---------------------------------------------------------------------------
// In-place normalization of attn: attn[row, :] *= 1/rowsum[row]
// ---------------------------------------------------------------------------
__global__ void attn_norm(float* __restrict__ P, const float* __restrict__ rs) {
    const size_t vidx = (size_t)blockIdx.x * blockDim.x + threadIdx.x;  // float4 index
    const size_t e = vidx * 4;
    const size_t row = e / kNS;   // all 4 elements share the row (kNS % 4 == 0)
    const float inv = 1.0f / rs[row];
    float4 x = *(const float4*)(P + e);
    x.x *= inv; x.y *= inv; x.z *= inv; x.w *= inv;
    *(float4*)(P + e) = x;
}

// ---------------------------------------------------------------------------
// Launch: 8 graph-capturable kernel launches, no allocations, no syncs.
// Output layout assumption: d_out = [ out (B*NQ*D floats) | attn (B*NQ*NS) ]
// ---------------------------------------------------------------------------
extern "C" void kernel_launch(void* const* d_in, const int* in_sizes, int n_in,
                              void* d_out, int out_size) {
    (void)in_sizes; (void)n_in; (void)out_size;
    const float* k     = (const float*)d_in[0];
    const float* v     = (const float*)d_in[1];
    const float* q     = (const float*)d_in[2];
    const float* idt   = (const float*)d_in[3];
    const float* mask  = (const float*)d_in[4];
    const float* W     = (const float*)d_in[5];
    const float* bias  = (const float*)d_in[6];
    const float* scale = (const float*)d_in[7];
    const float* attwt = (const float*)d_in[8];
    const float* orgwt = (const float*)d_in[9];

    float* out  = (float*)d_out;
    float* attn = out + (size_t)kB * kNQ * kD;

    float *qp = nullptr, *kp = nullptr, *rs = nullptr;
    cudaGetSymbolAddress((void**)&qp, g_qp);
    cudaGetSymbolAddress((void**)&kp, g_kp);
    cudaGetSymbolAddress((void**)&rs, g_rowsum);

    proj_gemm<<<dim3(kC / 128, kMQ / 128), 256>>>(q, W, bias, qp);
    proj_gemm<<<dim3(kC / 128, kMK / 128), 256>>>(k, W, bias, kp);
    l2norm_rows<<<kMQ, 256>>>(qp);
    l2norm_rows<<<kMK, 256>>>(kp);
    attn_p<<<dim3(kNS / 128, kNQ / 128, kB), 256>>>(qp, kp, mask, scale, attn);
    row_sum<<<kMQ, 256>>>(attn, rs);
    out_gemm<<<dim3(kD / 128, kNQ / 128, kB), 256>>>(attn, v, idt, rs, attwt, orgwt, out);

    const size_t nvec4 = (size_t)kB * kNQ * kNS / 4;
    attn_norm<<<(unsigned)(nvec4 / 256), 256>>>(attn, rs);
}

// round 3
// speedup vs baseline: 1.0568x; 1.0568x over previous
#include <cuda_runtime.h>
#include <math.h>
#include <stdint.h>

// Problem constants (AttentionBlock_32031866094255)
constexpr int kB  = 8;
constexpr int kNQ = 4096;
constexpr int kNS = 4096;
constexpr int kC  = 2048;
constexpr int kD  = 512;
constexpr int kMQ = kB * kNQ;   // 32768
constexpr int kMK = kB * kNS;   // 32768

// Scratch (allocation-free rule: __device__ globals)
__device__ float g_qp[(size_t)kMQ * kC];   // 268 MB
__device__ float g_kp[(size_t)kMK * kC];   // 268 MB
__device__ float g_rowsum[kMQ];

// ---------------------------------------------------------------------------
// Block-wide deterministic sum reduction (fixed tree -> deterministic).
// ---------------------------------------------------------------------------
__device__ __forceinline__ float block_reduce_sum(float v) {
    __shared__ float red[32];
    __shared__ float total;
    #pragma unroll
    for (int o = 16; o > 0; o >>= 1) v += __shfl_down_sync(0xffffffffu, v, o);
    const int lane = threadIdx.x & 31;
    const int w = threadIdx.x >> 5;
    if (lane == 0) red[w] = v;
    __syncthreads();
    if (w == 0) {
        v = (lane < (int)(blockDim.x >> 5)) ? red[lane] : 0.0f;
        #pragma unroll
        for (int o = 16; o > 0; o >>= 1) v += __shfl_down_sync(0xffffffffu, v, o);
        if (lane == 0) total = v;
    }
    __syncthreads();
    return total;
}

// ---------------------------------------------------------------------------
// Projection GEMM: Y[m,n] = sum_c X[m,c] * W[n,c] + bias[n]
// X: [M, kC] row-major, W: [kC, kC] row-major (both K-major -> A*B^T form)
// Tile 128x128, BK=16, 256 threads, 8x8 per thread.
// ---------------------------------------------------------------------------
__global__ __launch_bounds__(256, 2)
void proj_gemm(const float* __restrict__ X, const float* __restrict__ W,
               const float* __restrict__ bias, float* __restrict__ Y) {
    __shared__ float As[16][128];
    __shared__ float Bs[16][128];
    const int m0 = blockIdx.y * 128;
    const int n0 = blockIdx.x * 128;
    const int tid = threadIdx.x;
    const int tx = tid & 15;
    const int ty = tid >> 4;
    float acc[8][8] = {};
    for (int k0 = 0; k0 < kC; k0 += 16) {
        #pragma unroll
        for (int it = 0; it < 2; ++it) {
            const int idx = tid + it * 256;
            const int r  = idx >> 2;
            const int c4 = (idx & 3) * 4;
            float4 a = *(const float4*)(X + (size_t)(m0 + r) * kC + k0 + c4);
            As[c4 + 0][r] = a.x; As[c4 + 1][r] = a.y;
            As[c4 + 2][r] = a.z; As[c4 + 3][r] = a.w;
            float4 b = *(const float4*)(W + (size_t)(n0 + r) * kC + k0 + c4);
            Bs[c4 + 0][r] = b.x; Bs[c4 + 1][r] = b.y;
            Bs[c4 + 2][r] = b.z; Bs[c4 + 3][r] = b.w;
        }
        __syncthreads();
        #pragma unroll
        for (int k = 0; k < 16; ++k) {
            float a[8], b[8];
            *(float4*)&a[0] = *(const float4*)&As[k][ty * 8];
            *(float4*)&a[4] = *(const float4*)&As[k][ty * 8 + 4];
            *(float4*)&b[0] = *(const float4*)&Bs[k][tx * 8];
            *(float4*)&b[4] = *(const float4*)&Bs[k][tx * 8 + 4];
            #pragma unroll
            for (int i = 0; i < 8; ++i)
                #pragma unroll
                for (int j = 0; j < 8; ++j)
                    acc[i][j] = fmaf(a[i], b[j], acc[i][j]);
        }
        __syncthreads();
    }
    #pragma unroll
    for (int i = 0; i < 8; ++i) {
        const int m = m0 + ty * 8 + i;
        #pragma unroll
        for (int j = 0; j < 8; j += 4) {
            const int n = n0 + tx * 8 + j;
            float4 o;
            o.x = acc[i][j + 0] + bias[n + 0];
            o.y = acc[i][j + 1] + bias[n + 1];
            o.z = acc[i][j + 2] + bias[n + 2];
            o.w = acc[i][j + 3] + bias[n + 3];
            *(float4*)(Y + (size_t)m * kC + n) = o;
        }
    }
}

// ---------------------------------------------------------------------------
// In-place row l2norm over rows of length kC (matches ref: x / max(||x||, 1e-12))
// ---------------------------------------------------------------------------
__global__ void l2norm_rows(float* __restrict__ y) {
    float* p = y + (size_t)blockIdx.x * kC;
    float ss = 0.0f;
    #pragma unroll
    for (int i = threadIdx.x * 4; i < kC; i += 1024) {
        float4 v = *(const float4*)(p + i);
        ss += v.x * v.x + v.y * v.y + v.z * v.z + v.w * v.w;
    }
    const float tot = block_reduce_sum(ss);
    const float inv = 1.0f / fmaxf(sqrtf(tot), 1e-12f);
    #pragma unroll
    for (int i = threadIdx.x * 4; i < kC; i += 1024) {
        float4 v = *(const float4*)(p + i);
        v.x *= inv; v.y *= inv; v.z *= inv; v.w *= inv;
        *(float4*)(p + i) = v;
    }
}

// ---------------------------------------------------------------------------
// QK^T + fixed-max exp: P[b,q,s] = exp(scale*(qp.kp) - scale - 1000*mask[b,s])
// (cos <= 1 => max logit <= scale, so fixed max is exact; masked entries
//  underflow to 0.0f exactly as in the fp32 reference softmax.)
// Writes unnormalized P directly into the attn output region.
// ---------------------------------------------------------------------------
__global__ __launch_bounds__(256, 2)
void attn_p(const float* __restrict__ qp, const float* __restrict__ kp,
            const float* __restrict__ mask, const float* __restrict__ scale_ptr,
            float* __restrict__ P) {
    __shared__ float As[16][128];
    __shared__ float Bs[16][128];
    const int b = blockIdx.z;
    const float* A  = qp + (size_t)b * kNQ * kC;
    const float* Bm = kp + (size_t)b * kNS * kC;
    const int m0 = blockIdx.y * 128;
    const int n0 = blockIdx.x * 128;
    const int tid = threadIdx.x;
    const int tx = tid & 15;
    const int ty = tid >> 4;
    float acc[8][8] = {};
    for (int k0 = 0; k0 < kC; k0 += 16) {
        #pragma unroll
        for (int it = 0; it < 2; ++it) {
            const int idx = tid + it * 256;
            const int r  = idx >> 2;
            const int c4 = (idx & 3) * 4;
            float4 a = *(const float4*)(A + (size_t)(m0 + r) * kC + k0 + c4);
            As[c4 + 0][r] = a.x; As[c4 + 1][r] = a.y;
            As[c4 + 2][r] = a.z; As[c4 + 3][r] = a.w;
            float4 bb = *(const float4*)(Bm + (size_t)(n0 + r) * kC + k0 + c4);
            Bs[c4 + 0][r] = bb.x; Bs[c4 + 1][r] = bb.y;
            Bs[c4 + 2][r] = bb.z; Bs[c4 + 3][r] = bb.w;
        }
        __syncthreads();
        #pragma unroll
        for (int k = 0; k < 16; ++k) {
            float a[8], b[8];
            *(float4*)&a[0] = *(const float4*)&As[k][ty * 8];
            *(float4*)&a[4] = *(const float4*)&As[k][ty * 8 + 4];
            *(float4*)&b[0] = *(const float4*)&Bs[k][tx * 8];
            *(float4*)&b[4] = *(const float4*)&Bs[k][tx * 8 + 4];
            #pragma unroll
            for (int i = 0; i < 8; ++i)
                #pragma unroll
                for (int j = 0; j < 8; ++j)
                    acc[i][j] = fmaf(a[i], b[j], acc[i][j]);
        }
        __syncthreads();
    }
    const float sc = scale_ptr[0];
    float mk[8];
    #pragma unroll
    for (int j = 0; j < 8; ++j)
        mk[j] = mask[(size_t)b * kNS + n0 + tx * 8 + j];
    #pragma unroll
    for (int i = 0; i < 8; ++i) {
        const int m = m0 + ty * 8 + i;
        float* prow = P + ((size_t)b * kNQ + m) * kNS + n0 + tx * 8;
        #pragma unroll
        for (int j = 0; j < 8; j += 4) {
            float4 o;
            o.x = expf(sc * acc[i][j + 0] - sc - 1000.0f * mk[j + 0]);
            o.y = expf(sc * acc[i][j + 1] - sc - 1000.0f * mk[j + 1]);
            o.z = expf(sc * acc[i][j + 2] - sc - 1000.0f * mk[j + 2]);
            o.w = expf(sc * acc[i][j + 3] - sc - 1000.0f * mk[j + 3]);
            *(float4*)(prow + j) = o;
        }
    }
}

// ---------------------------------------------------------------------------
// Deterministic row sums of unnormalized P (one block per (b,q) row).
// ---------------------------------------------------------------------------
__global__ void row_sum(const float* __restrict__ P, float* __restrict__ rs) {
    const float* p = P + (size_t)blockIdx.x * kNS;
    float s = 0.0f;
    #pragma unroll
    for (int i = threadIdx.x * 4; i < kNS; i += 1024) {
        float4 v = *(const float4*)(p + i);
        s += v.x + v.y + v.z + v.w;
    }
    const float tot = block_reduce_sum(s);
    if (threadIdx.x == 0) rs[blockIdx.x] = tot;
}

// ---------------------------------------------------------------------------
// out[b,q,d] = att_wt * (sum_s P[b,q,s] * v[b,s,d]) / rowsum[b,q] + org_wt*idt
// A = P (K-major), B = v (N-major). Tile 128x128, BK=16.
// ---------------------------------------------------------------------------
__global__ __launch_bounds__(256, 2)
void out_gemm(const float* __restrict__ P, const float* __restrict__ V,
              const float* __restrict__ idt, const float* __restrict__ rs,
              const float* __restrict__ attwt, const float* __restrict__ orgwt,
              float* __restrict__ out) {
    __shared__ float As[16][128];
    __shared__ float Bs[16][128];
    const int b = blockIdx.z;
    const float* A  = P + (size_t)b * kNQ * kNS;
    const float* Bv = V + (size_t)b * kNS * kD;
    const int m0 = blockIdx.y * 128;
    const int n0 = blockIdx.x * 128;
    const int tid = threadIdx.x;
    const int tx = tid & 15;
    const int ty = tid >> 4;
    float acc[8][8] = {};
    for (int k0 = 0; k0 < kNS; k0 += 16) {
        #pragma unroll
        for (int it = 0; it < 2; ++it) {
            const int idx = tid + it * 256;
            const int r  = idx >> 2;
            const int c4 = (idx & 3) * 4;
            float4 a = *(const float4*)(A + (size_t)(m0 + r) * kNS + k0 + c4);
            As[c4 + 0][r] = a.x; As[c4 + 1][r] = a.y;
            As[c4 + 2][r] = a.z; As[c4 + 3][r] = a.w;
            const int br = idx >> 5;          // 16 rows
            const int bc = (idx & 31) * 4;    // 128 cols
            float4 v = *(const float4*)(Bv + (size_t)(k0 + br) * kD + n0 + bc);
            *(float4*)&Bs[br][bc] = v;
        }
        __syncthreads();
        #pragma unroll
        for (int k = 0; k < 16; ++k) {
            float a[8], b[8];
            *(float4*)&a[0] = *(const float4*)&As[k][ty * 8];
            *(float4*)&a[4] = *(const float4*)&As[k][ty * 8 + 4];
            *(float4*)&b[0] = *(const float4*)&Bs[k][tx * 8];
            *(float4*)&b[4] = *(const float4*)&Bs[k][tx * 8 + 4];
            #pragma unroll
            for (int i = 0; i < 8; ++i)
                #pragma unroll
                for (int j = 0; j < 8; ++j)
                    acc[i][j] = fmaf(a[i], b[j], acc[i][j]);
        }
        __syncthreads();
    }
    const float aw = attwt[0];
    const float ow = orgwt[0];
    #pragma unroll
    for (int i = 0; i < 8; ++i) {
        const int m = m0 + ty * 8 + i;
        const float inv = 1.0f / rs[(size_t)b * kNQ + m];
        const float* irow = idt + ((size_t)b * kNQ + m) * kD + n0 + tx * 8;
        float* orow = out + ((size_t)b * kNQ + m) * kD + n0 + tx * 8;
        #pragma unroll
        for (int j = 0; j < 8; j += 4) {
            float4 id4 = *(const float4*)(irow + j);
            float4 o;
            o.x = aw * acc[i][j + 0] * inv + ow * id4.x;
            o.y = aw * acc[i][j + 1] * inv + ow * id4.y;
            o.z = aw * acc[i][j + 2] * inv + ow * id4.z;
            o.w = aw * acc[i][j + 3] * inv + ow * id4.w;
            *(float4*)(orow + j) = o;
        }
    }
}

// ---------------------------------------------------------------------------
// In-place normalization of attn: attn[row, :] *= 1/rowsum[row]
// ---------------------------------------------------------------------------
__global__ void attn_norm(float* __restrict__ P, const float* __restrict__ rs) {
    const size_t vidx = (size_t)blockIdx.x * blockDim.x + threadIdx.x;  // float4 index
    const size_t e = vidx * 4;
    const size_t row = e / kNS;   // all 4 elements share the row (kNS % 4 == 0)
    const float inv = 1.0f / rs[row];
    float4 x = *(const float4*)(P + e);
    x.x *= inv; x.y *= inv; x.z *= inv; x.w *= inv;
    *(float4*)(P + e) = x;
}

// ---------------------------------------------------------------------------
// Launch: 8 graph-capturable kernel launches, no allocations, no syncs.
// Output layout assumption: d_out = [ out (B*NQ*D floats) | attn (B*NQ*NS) ]
// ---------------------------------------------------------------------------
extern "C" void kernel_launch(void* const* d_in, const int* in_sizes, int n_in,
                              void* d_out, int out_size) {
    (void)in_sizes; (void)n_in; (void)out_size;
    const float* k     = (const float*)d_in[0];
    const float* v     = (const float*)d_in[1];
    const float* q     = (const float*)d_in[2];
    const float* idt   = (const float*)d_in[3];
    const float* mask  = (const float*)d_in[4];
    const float* W     = (const float*)d_in[5];
    const float* bias  = (const float*)d_in[6];
    const float* scale = (const float*)d_in[7];
    const float* attwt = (const float*)d_in[8];
    const float* orgwt = (const float*)d_in[9];

    float* out  = (float*)d_out;
    float* attn = out + (size_t)kB * kNQ * kD;

    float *qp = nullptr, *kp = nullptr, *rs = nullptr;
    cudaGetSymbolAddress((void**)&qp, g_qp);
    cudaGetSymbolAddress((void**)&kp, g_kp);
    cudaGetSymbolAddress((void**)&rs, g_rowsum);

    proj_gemm<<<dim3(kC / 128, kMQ / 128), 256>>>(q, W, bias, qp);
    proj_gemm<<<dim3(kC / 128, kMK / 128), 256>>>(k, W, bias, kp);
    l2norm_rows<<<kMQ, 256>>>(qp);
    l2norm_rows<<<kMK, 256>>>(kp);
    attn_p<<<dim3(kNS / 128, kNQ / 128, kB), 256>>>(qp, kp, mask, scale, attn);
    row_sum<<<kMQ, 256>>>(attn, rs);
    out_gemm<<<dim3(kD / 128, kNQ / 128, kB), 256>>>(attn, v, idt, rs, attwt, orgwt, out);

    const size_t nvec4 = (size_t)kB * kNQ * kNS / 4;
    attn_norm<<<(unsigned)(nvec4 / 256), 256>>>(attn, rs);
}

// round 6
// speedup vs baseline: 2.7734x; 2.6243x over previous
#include <cuda_runtime.h>
#include <cuda_fp16.h>
#include <math.h>
#include <stdint.h>

constexpr int kB  = 8;
constexpr int kNQ = 4096;
constexpr int kNS = 4096;
constexpr int kC  = 2048;
constexpr int kD  = 512;
constexpr int kMQ = kB * kNQ;   // 32768
constexpr int kMK = kB * kNS;   // 32768

// Scratch (__device__ globals; allocation-free rule)
__device__ __half g_ah[(size_t)kMQ * kC];
__device__ __half g_al[(size_t)kMQ * kC];
__device__ __half g_bh[(size_t)kMK * kC];
__device__ __half g_bl[(size_t)kMK * kC];
__device__ __half g_wh[(size_t)kC * kC];
__device__ __half g_wl[(size_t)kC * kC];
__device__ __half g_vt[(size_t)kB * kD * kNS];   // v transposed [b, d, s] fp16
__device__ __half g_ph[(size_t)kMQ * kNS];       // NORMALIZED attn weights fp16
__device__ float  g_qp[(size_t)kMQ * kC];
__device__ float  g_kp[(size_t)kMK * kC];
__device__ float  g_rowsum[kMQ];

// ---------------- helpers ----------------
__device__ __forceinline__ uint32_t smem_u32(const void* p) {
    uint32_t a;
    asm("{ .reg .u64 t; cvta.to.shared.u64 t, %1; cvt.u32.u64 %0, t; }" : "=r"(a) : "l"(p));
    return a;
}
__device__ __forceinline__ void ldm4(uint32_t r[4], uint32_t addr) {
    asm volatile("ldmatrix.sync.aligned.m8n8.x4.shared.b16 {%0,%1,%2,%3}, [%4];"
                 : "=r"(r[0]), "=r"(r[1]), "=r"(r[2]), "=r"(r[3]) : "r"(addr));
}
__device__ __forceinline__ void mma16816(float c[4], const uint32_t a[4],
                                         uint32_t b0, uint32_t b1) {
    asm volatile(
        "mma.sync.aligned.m16n8k16.row.col.f32.f16.f16.f32 "
        "{%0,%1,%2,%3}, {%4,%5,%6,%7}, {%8,%9}, {%0,%1,%2,%3};"
        : "+f"(c[0]), "+f"(c[1]), "+f"(c[2]), "+f"(c[3])
        : "r"(a[0]), "r"(a[1]), "r"(a[2]), "r"(a[3]), "r"(b0), "r"(b1));
}

// Tile geometry: block 128x128, BK=64 fp16, rows padded to 144 B (conflict-free)
constexpr int BK = 64;
constexpr uint32_t ROWB = 144;                 // bytes per padded SMEM row
constexpr uint32_t TS   = 128 * ROWB;          // 18432 B per tile

// Load a 128 x 64 (fp16) K-major tile into padded SMEM via cp.async (16B chunks)
__device__ __forceinline__ void load_tile(uint32_t dst, const __half* src, int ldk) {
    const int tid = threadIdx.x;
    #pragma unroll
    for (int i = 0; i < 4; ++i) {
        const int idx = tid + i * 256;      // 1024 chunks: 128 rows x 8 segs
        const int row = idx >> 3;
        const int seg = idx & 7;
        asm volatile("cp.async.cg.shared.global [%0], [%1], 16;"
                     :: "r"(dst + row * ROWB + seg * 16),
                        "l"(src + (size_t)row * ldk + seg * 8) : "memory");
    }
}

// ---------------------------------------------------------------------------
// HMMA mainloop: acc[2][8][4] accumulates C[128][128] for this block.
// NSPLIT==3: C = Ah*Bh' + Al*Bh' + Ah*Bl'    NSPLIT==1: C = Ah*Bh'
// 8 warps as 4(m) x 2(n); warp tile 32x64.
// ---------------------------------------------------------------------------
template<int NSPLIT>
__device__ __forceinline__ void hmma_mainloop(
    const __half* Ah, const __half* Al, const __half* Bh, const __half* Bl,
    int lda, int ldb, int K, char* smem, float acc[2][8][4])
{
    const int tid  = threadIdx.x;
    const int wid  = tid >> 5;
    const int lane = tid & 31;
    const int wm   = wid >> 1;      // 0..3 -> m offset wm*32
    const int wn   = wid & 1;       // 0..1 -> n offset wn*64
    constexpr uint32_t STAGE = (NSPLIT == 3) ? 4 * TS : 2 * TS;
    constexpr uint32_t BOFF  = (NSPLIT == 3) ? 2 * TS : TS;
    const uint32_t sb = smem_u32(smem);
    const int NK = K / BK;

    load_tile(sb, Ah, lda);
    if constexpr (NSPLIT == 3) load_tile(sb + TS, Al, lda);
    load_tile(sb + BOFF, Bh, ldb);
    if constexpr (NSPLIT == 3) load_tile(sb + 3 * TS, Bl, ldb);
    asm volatile("cp.async.commit_group;");

    const uint32_t a_lane_off = (uint32_t)((lane & 15) * ROWB + ((lane >> 4) * 8) * 2);

    for (int kc = 0; kc < NK; ++kc) {
        if (kc + 1 < NK) {
            const uint32_t s = sb + ((kc + 1) & 1) * STAGE;
            const size_t k0 = (size_t)(kc + 1) * BK;
            load_tile(s, Ah + k0, lda);
            if constexpr (NSPLIT == 3) load_tile(s + TS, Al + k0, lda);
            load_tile(s + BOFF, Bh + k0, ldb);
            if constexpr (NSPLIT == 3) load_tile(s + 3 * TS, Bl + k0, ldb);
            asm volatile("cp.async.commit_group;");
            asm volatile("cp.async.wait_group 1;");
        } else {
            asm volatile("cp.async.wait_group 0;");
        }
        __syncthreads();

        const uint32_t abase = sb + (kc & 1) * STAGE + wm * 32 * ROWB + a_lane_off;
        const uint32_t bbase = sb + (kc & 1) * STAGE + BOFF + wn * 64 * ROWB + a_lane_off;

        #pragma unroll
        for (int ks = 0; ks < 4; ++ks) {
            const uint32_t kb = ks * 32;  // bytes: ks*16 halves
            uint32_t ah[2][4], al[2][4], bh[4][4], bl[4][4];
            #pragma unroll
            for (int mt = 0; mt < 2; ++mt) {
                const uint32_t a = abase + mt * 16 * ROWB + kb;
                ldm4(ah[mt], a);
                if constexpr (NSPLIT == 3) ldm4(al[mt], a + TS);
            }
            #pragma unroll
            for (int np = 0; np < 4; ++np) {
                const uint32_t a = bbase + np * 16 * ROWB + kb;
                ldm4(bh[np], a);
                if constexpr (NSPLIT == 3) ldm4(bl[np], a + TS);
            }
            #pragma unroll
            for (int mt = 0; mt < 2; ++mt)
                #pragma unroll
                for (int np = 0; np < 4; ++np)
                    #pragma unroll
                    for (int h = 0; h < 2; ++h) {
                        float* c = acc[mt][np * 2 + h];
                        mma16816(c, ah[mt], bh[np][h], bh[np][h + 2]);
                        if constexpr (NSPLIT == 3) {
                            mma16816(c, al[mt], bh[np][h], bh[np][h + 2]);
                            mma16816(c, ah[mt], bl[np][h], bl[np][h + 2]);
                        }
                    }
        }
        __syncthreads();
    }
}

constexpr unsigned SMEM_SPLIT = 8 * TS;   // 147456
constexpr unsigned SMEM_PV    = 4 * TS;   // 73728

// ---------------- GEMM kernels (epilogue fused from fragments) ----------------
__global__ __launch_bounds__(256, 1)
void gemm_proj_k(const __half* __restrict__ Ah, const __half* __restrict__ Al,
                 const __half* __restrict__ Wh, const __half* __restrict__ Wl,
                 const float* __restrict__ bias, float* __restrict__ Y) {
    extern __shared__ char smem[];
    const int m0 = blockIdx.y * 128, n0 = blockIdx.x * 128;
    float acc[2][8][4] = {};
    hmma_mainloop<3>(Ah + (size_t)m0 * kC, Al + (size_t)m0 * kC,
                     Wh + (size_t)n0 * kC, Wl + (size_t)n0 * kC, kC, kC, kC, smem, acc);
    const int wid = threadIdx.x >> 5, lane = threadIdx.x & 31;
    const int wm = wid >> 1, wn = wid & 1;
    #pragma unroll
    for (int mt = 0; mt < 2; ++mt)
        #pragma unroll
        for (int nt = 0; nt < 8; ++nt) {
            const int r0 = m0 + wm * 32 + mt * 16 + (lane >> 2);
            const int c  = n0 + wn * 64 + nt * 8 + (lane & 3) * 2;
            const float* a = acc[mt][nt];
            *(float2*)(Y + (size_t)r0 * kC + c) =
                make_float2(a[0] + bias[c], a[1] + bias[c + 1]);
            *(float2*)(Y + (size_t)(r0 + 8) * kC + c) =
                make_float2(a[2] + bias[c], a[3] + bias[c + 1]);
        }
}

__global__ __launch_bounds__(256, 1)
void gemm_attn_k(const __half* __restrict__ qh, const __half* __restrict__ ql,
                 const __half* __restrict__ kh, const __half* __restrict__ kl,
                 const float* __restrict__ mask, const float* __restrict__ scale_ptr,
                 float* __restrict__ P32) {
    extern __shared__ char smem[];
    const int b = blockIdx.z;
    const int m0 = blockIdx.y * 128, n0 = blockIdx.x * 128;
    const size_t aoff = ((size_t)b * kNQ + m0) * kC;
    const size_t boff = ((size_t)b * kNS + n0) * kC;
    float acc[2][8][4] = {};
    hmma_mainloop<3>(qh + aoff, ql + aoff, kh + boff, kl + boff, kC, kC, kC, smem, acc);
    const int wid = threadIdx.x >> 5, lane = threadIdx.x & 31;
    const int wm = wid >> 1, wn = wid & 1;
    const float sc = scale_ptr[0];
    #pragma unroll
    for (int mt = 0; mt < 2; ++mt)
        #pragma unroll
        for (int nt = 0; nt < 8; ++nt) {
            const int r0 = m0 + wm * 32 + mt * 16 + (lane >> 2);
            const int c  = n0 + wn * 64 + nt * 8 + (lane & 3) * 2;
            const float* a = acc[mt][nt];
            const float mk0 = mask[(size_t)b * kNS + c];
            const float mk1 = mask[(size_t)b * kNS + c + 1];
            const float e0 = __expf(sc * a[0] - sc - 1000.0f * mk0);
            const float e1 = __expf(sc * a[1] - sc - 1000.0f * mk1);
            const float e2 = __expf(sc * a[2] - sc - 1000.0f * mk0);
            const float e3 = __expf(sc * a[3] - sc - 1000.0f * mk1);
            const size_t rb0 = ((size_t)b * kNQ + r0) * kNS + c;
            const size_t rb1 = rb0 + (size_t)8 * kNS;
            *(float2*)(P32 + rb0) = make_float2(e0, e1);
            *(float2*)(P32 + rb1) = make_float2(e2, e3);
        }
}

__global__ __launch_bounds__(256, 1)
void gemm_pv_k(const __half* __restrict__ Ph, const __half* __restrict__ Vt,
               const float* __restrict__ idt,
               const float* __restrict__ awp, const float* __restrict__ owp,
               float* __restrict__ out) {
    extern __shared__ char smem[];
    const int m0 = blockIdx.y * 128;     // row over kMQ (128 | kNQ)
    const int n0 = blockIdx.x * 128;     // d
    const int b  = m0 / kNQ;
    float acc[2][8][4] = {};
    hmma_mainloop<1>(Ph + (size_t)m0 * kNS, nullptr,
                     Vt + ((size_t)b * kD + n0) * kNS, nullptr, kNS, kNS, kNS, smem, acc);
    const int wid = threadIdx.x >> 5, lane = threadIdx.x & 31;
    const int wm = wid >> 1, wn = wid & 1;
    const float aw = awp[0], ow = owp[0];
    #pragma unroll
    for (int mt = 0; mt < 2; ++mt) {
        const int r0 = m0 + wm * 32 + mt * 16 + (lane >> 2);
        #pragma unroll
        for (int nt = 0; nt < 8; ++nt) {
            const int c = n0 + wn * 64 + nt * 8 + (lane & 3) * 2;
            const float* a = acc[mt][nt];
            const float2 d0 = *(const float2*)(idt + (size_t)r0 * kD + c);
            const float2 d1 = *(const float2*)(idt + (size_t)(r0 + 8) * kD + c);
            *(float2*)(out + (size_t)r0 * kD + c) =
                make_float2(aw * a[0] + ow * d0.x, aw * a[1] + ow * d0.y);
            *(float2*)(out + (size_t)(r0 + 8) * kD + c) =
                make_float2(aw * a[2] + ow * d1.x, aw * a[3] + ow * d1.y);
        }
    }
}

// ---------------- support kernels ----------------
__device__ __forceinline__ float block_reduce_sum(float v) {
    __shared__ float red[32];
    __shared__ float total;
    #pragma unroll
    for (int o = 16; o > 0; o >>= 1) v += __shfl_down_sync(0xffffffffu, v, o);
    const int lane = threadIdx.x & 31, w = threadIdx.x >> 5;
    if (lane == 0) red[w] = v;
    __syncthreads();
    if (w == 0) {
        v = (lane < (int)(blockDim.x >> 5)) ? red[lane] : 0.0f;
        #pragma unroll
        for (int o = 16; o > 0; o >>= 1) v += __shfl_down_sync(0xffffffffu, v, o);
        if (lane == 0) total = v;
    }
    __syncthreads();
    return total;
}

__global__ void split_f32(const float* __restrict__ x, __half* __restrict__ hi,
                          __half* __restrict__ lo, size_t n4) {
    const size_t i = (size_t)blockIdx.x * blockDim.x + threadIdx.x;
    if (i >= n4) return;
    const float4 v = ((const float4*)x)[i];
    const __half h0 = __float2half_rn(v.x), h1 = __float2half_rn(v.y);
    const __half h2 = __float2half_rn(v.z), h3 = __float2half_rn(v.w);
    ((__half2*)hi)[2 * i]     = __halves2half2(h0, h1);
    ((__half2*)hi)[2 * i + 1] = __halves2half2(h2, h3);
    ((__half2*)lo)[2 * i]     = __halves2half2(__float2half_rn(v.x - __half2float(h0)),
                                               __float2half_rn(v.y - __half2float(h1)));
    ((__half2*)lo)[2 * i + 1] = __halves2half2(__float2half_rn(v.z - __half2float(h2)),
                                               __float2half_rn(v.w - __half2float(h3)));
}

__global__ void l2norm_split(const float* __restrict__ src, __half* __restrict__ hi,
                             __half* __restrict__ lo) {
    const float* p = src + (size_t)blockIdx.x * kC;
    float ss = 0.0f;
    #pragma unroll
    for (int i = threadIdx.x * 4; i < kC; i += 1024) {
        const float4 v = *(const float4*)(p + i);
        ss += v.x * v.x + v.y * v.y + v.z * v.z + v.w * v.w;
    }
    const float tot = block_reduce_sum(ss);
    const float inv = 1.0f / fmaxf(sqrtf(tot), 1e-12f);
    __half* ho = hi + (size_t)blockIdx.x * kC;
    __half* lg = lo + (size_t)blockIdx.x * kC;
    #pragma unroll
    for (int i = threadIdx.x * 4; i < kC; i += 1024) {
        const float4 v = *(const float4*)(p + i);
        const float x0 = v.x * inv, x1 = v.y * inv, x2 = v.z * inv, x3 = v.w * inv;
        const __half h0 = __float2half_rn(x0), h1 = __float2half_rn(x1);
        const __half h2 = __float2half_rn(x2), h3 = __float2half_rn(x3);
        *(__half2*)(ho + i)     = __halves2half2(h0, h1);
        *(__half2*)(ho + i + 2) = __halves2half2(h2, h3);
        *(__half2*)(lg + i)     = __halves2half2(__float2half_rn(x0 - __half2float(h0)),
                                                 __float2half_rn(x1 - __half2float(h1)));
        *(__half2*)(lg + i + 2) = __halves2half2(__float2half_rn(x2 - __half2float(h2)),
                                                 __float2half_rn(x3 - __half2float(h3)));
    }
}

__global__ void transpose_v(const float* __restrict__ v, __half* __restrict__ vt) {
    __shared__ float t[32][33];
    const int b  = blockIdx.z;
    const int s0 = blockIdx.x * 32;
    const int d0 = blockIdx.y * 32;
    const int tx = threadIdx.x, ty = threadIdx.y;
    #pragma unroll
    for (int i = 0; i < 32; i += 8)
        t[ty + i][tx] = v[((size_t)b * kNS + s0 + ty + i) * kD + d0 + tx];
    __syncthreads();
    #pragma unroll
    for (int i = 0; i < 32; i += 8)
        vt[((size_t)b * kD + d0 + ty + i) * kNS + s0 + tx] = __float2half_rn(t[tx][ty + i]);
}

__global__ void row_sum(const float* __restrict__ P, float* __restrict__ rs) {
    const float* p = P + (size_t)blockIdx.x * kNS;
    float s = 0.0f;
    #pragma unroll
    for (int i = threadIdx.x * 4; i < kNS; i += 1024) {
        const float4 v = *(const float4*)(p + i);
        s += v.x + v.y + v.z + v.w;
    }
    const float tot = block_reduce_sum(s);
    if (threadIdx.x == 0) rs[blockIdx.x] = tot;
}

// Normalize attn in place AND emit fp16 normalized weights for the PV GEMM.
// (Normalizing BEFORE the fp16 cast keeps values ~1/4096 — fp16-normal range —
//  instead of ~e^-20, which underflowed fp16 and broke Round 5.)
__global__ void attn_norm(float* __restrict__ P, const float* __restrict__ rs,
                          __half* __restrict__ Ph) {
    const size_t e = ((size_t)blockIdx.x * blockDim.x + threadIdx.x) * 4;
    const float inv = 1.0f / rs[e / kNS];
    float4 x = *(const float4*)(P + e);
    x.x *= inv; x.y *= inv; x.z *= inv; x.w *= inv;
    *(float4*)(P + e) = x;
    *(__half2*)(Ph + e)     = __floats2half2_rn(x.x, x.y);
    *(__half2*)(Ph + e + 2) = __floats2half2_rn(x.z, x.w);
}

// ---------------- launch ----------------
extern "C" void kernel_launch(void* const* d_in, const int* in_sizes, int n_in,
                              void* d_out, int out_size) {
    (void)in_sizes; (void)n_in; (void)out_size;
    const float* k     = (const float*)d_in[0];
    const float* v     = (const float*)d_in[1];
    const float* q     = (const float*)d_in[2];
    const float* idt   = (const float*)d_in[3];
    const float* mask  = (const float*)d_in[4];
    const float* W     = (const float*)d_in[5];
    const float* bias  = (const float*)d_in[6];
    const float* scale = (const float*)d_in[7];
    const float* attwt = (const float*)d_in[8];
    const float* orgwt = (const float*)d_in[9];

    float* out  = (float*)d_out;
    float* attn = out + (size_t)kB * kNQ * kD;

    __half *ah, *al, *bh, *bl, *wh, *wl, *vt, *ph;
    float *qp, *kp, *rs;
    cudaGetSymbolAddress((void**)&ah, g_ah);
    cudaGetSymbolAddress((void**)&al, g_al);
    cudaGetSymbolAddress((void**)&bh, g_bh);
    cudaGetSymbolAddress((void**)&bl, g_bl);
    cudaGetSymbolAddress((void**)&wh, g_wh);
    cudaGetSymbolAddress((void**)&wl, g_wl);
    cudaGetSymbolAddress((void**)&vt, g_vt);
    cudaGetSymbolAddress((void**)&ph, g_ph);
    cudaGetSymbolAddress((void**)&qp, g_qp);
    cudaGetSymbolAddress((void**)&kp, g_kp);
    cudaGetSymbolAddress((void**)&rs, g_rowsum);

    static bool attr_done = false;
    if (!attr_done) {
        cudaFuncSetAttribute(gemm_proj_k, cudaFuncAttributeMaxDynamicSharedMemorySize, SMEM_SPLIT);
        cudaFuncSetAttribute(gemm_attn_k, cudaFuncAttributeMaxDynamicSharedMemorySize, SMEM_SPLIT);
        cudaFuncSetAttribute(gemm_pv_k,   cudaFuncAttributeMaxDynamicSharedMemorySize, SMEM_PV);
        attr_done = true;
    }

    const size_t nq4 = (size_t)kMQ * kC / 4;
    split_f32<<<(unsigned)((nq4 + 255) / 256), 256>>>(q, ah, al, nq4);
    split_f32<<<(unsigned)((nq4 + 255) / 256), 256>>>(k, bh, bl, nq4);
    const size_t nw4 = (size_t)kC * kC / 4;
    split_f32<<<(unsigned)((nw4 + 255) / 256), 256>>>(W, wh, wl, nw4);
    transpose_v<<<dim3(kNS / 32, kD / 32, kB), dim3(32, 8)>>>(v, vt);

    gemm_proj_k<<<dim3(kC / 128, kMQ / 128), 256, SMEM_SPLIT>>>(ah, al, wh, wl, bias, qp);
    gemm_proj_k<<<dim3(kC / 128, kMK / 128), 256, SMEM_SPLIT>>>(bh, bl, wh, wl, bias, kp);

    l2norm_split<<<kMQ, 256>>>(qp, ah, al);
    l2norm_split<<<kMK, 256>>>(kp, bh, bl);

    gemm_attn_k<<<dim3(kNS / 128, kNQ / 128, kB), 256, SMEM_SPLIT>>>(ah, al, bh, bl,
                                                                     mask, scale, attn);
    row_sum<<<kMQ, 256>>>(attn, rs);

    const size_t nvec4 = (size_t)kB * kNQ * kNS / 4;
    attn_norm<<<(unsigned)(nvec4 / 256), 256>>>(attn, rs, ph);

    gemm_pv_k<<<dim3(kD / 128, kMQ / 128), 256, SMEM_PV>>>(ph, vt, idt, attwt, orgwt, out);
}

// round 7
// speedup vs baseline: 4.5751x; 1.6496x over previous
#include <cuda_runtime.h>
#include <cuda_fp16.h>
#include <math.h>
#include <stdint.h>

constexpr int kB  = 8;
constexpr int kNQ = 4096;
constexpr int kNS = 4096;
constexpr int kC  = 2048;
constexpr int kD  = 512;
constexpr int kMQ = kB * kNQ;   // 32768
constexpr int kMK = kB * kNS;   // 32768

// Scratch (__device__ globals; allocation-free rule)
__device__ __half g_ah[(size_t)kMQ * kC];        // q hi -> later qp hi
__device__ __half g_al[(size_t)kMQ * kC];        // qp lo
__device__ __half g_bh[(size_t)kMK * kC];        // k hi -> later kp hi
__device__ __half g_eh[(size_t)kC * kC];         // E = W - I, fp16
__device__ __half g_vt[(size_t)kB * kD * kNS];   // v transposed [b, d, s] fp16
__device__ __half g_ph[(size_t)kMQ * kNS];       // NORMALIZED attn weights fp16
__device__ float  g_qp[(size_t)kMQ * kC];
__device__ float  g_kp[(size_t)kMK * kC];
__device__ float  g_rowsum[kMQ];

// ---------------- helpers ----------------
__device__ __forceinline__ uint32_t smem_u32(const void* p) {
    uint32_t a;
    asm("{ .reg .u64 t; cvta.to.shared.u64 t, %1; cvt.u32.u64 %0, t; }" : "=r"(a) : "l"(p));
    return a;
}
__device__ __forceinline__ void ldm4(uint32_t r[4], uint32_t addr) {
    asm volatile("ldmatrix.sync.aligned.m8n8.x4.shared.b16 {%0,%1,%2,%3}, [%4];"
                 : "=r"(r[0]), "=r"(r[1]), "=r"(r[2]), "=r"(r[3]) : "r"(addr));
}
__device__ __forceinline__ void mma16816(float c[4], const uint32_t a[4],
                                         uint32_t b0, uint32_t b1) {
    asm volatile(
        "mma.sync.aligned.m16n8k16.row.col.f32.f16.f16.f32 "
        "{%0,%1,%2,%3}, {%4,%5,%6,%7}, {%8,%9}, {%0,%1,%2,%3};"
        : "+f"(c[0]), "+f"(c[1]), "+f"(c[2]), "+f"(c[3])
        : "r"(a[0]), "r"(a[1]), "r"(a[2]), "r"(a[3]), "r"(b0), "r"(b1));
}

// Tile geometry: block 128x128, BK=64 fp16, rows padded to 144 B (conflict-free)
constexpr int BK = 64;
constexpr uint32_t ROWB = 144;
constexpr uint32_t TS   = 128 * ROWB;          // 18432 B per tile

// Load a 128 x 64 (fp16) K-major tile into padded SMEM via cp.async (16B chunks)
__device__ __forceinline__ void load_tile(uint32_t dst, const __half* src, int ldk) {
    const int tid = threadIdx.x;
    #pragma unroll
    for (int i = 0; i < 4; ++i) {
        const int idx = tid + i * 256;      // 1024 chunks: 128 rows x 8 segs
        const int row = idx >> 3;
        const int seg = idx & 7;
        asm volatile("cp.async.cg.shared.global [%0], [%1], 16;"
                     :: "r"(dst + row * ROWB + seg * 16),
                        "l"(src + (size_t)row * ldk + seg * 8) : "memory");
    }
}

// ---------------------------------------------------------------------------
// HMMA mainloop: acc[2][8][4] accumulates C[128][128] for this block.
// NTERMS==2: C = Ah*Bh' + Al*Bh' (A hi/lo split)   NTERMS==1: C = Ah*Bh'
// 8 warps as 4(m) x 2(n); warp tile 32x64.
// ---------------------------------------------------------------------------
template<int NTERMS>
__device__ __forceinline__ void hmma_mainloop(
    const __half* Ah, const __half* Al, const __half* Bh,
    int lda, int ldb, int K, char* smem, float acc[2][8][4])
{
    const int tid  = threadIdx.x;
    const int wid  = tid >> 5;
    const int lane = tid & 31;
    const int wm   = wid >> 1;
    const int wn   = wid & 1;
    constexpr uint32_t STAGE = (NTERMS + 1) * TS;
    constexpr uint32_t BOFF  = NTERMS * TS;
    const uint32_t sb = smem_u32(smem);
    const int NK = K / BK;

    load_tile(sb, Ah, lda);
    if constexpr (NTERMS == 2) load_tile(sb + TS, Al, lda);
    load_tile(sb + BOFF, Bh, ldb);
    asm volatile("cp.async.commit_group;");

    const uint32_t a_lane_off = (uint32_t)((lane & 15) * ROWB + ((lane >> 4) * 8) * 2);

    for (int kc = 0; kc < NK; ++kc) {
        if (kc + 1 < NK) {
            const uint32_t s = sb + ((kc + 1) & 1) * STAGE;
            const size_t k0 = (size_t)(kc + 1) * BK;
            load_tile(s, Ah + k0, lda);
            if constexpr (NTERMS == 2) load_tile(s + TS, Al + k0, lda);
            load_tile(s + BOFF, Bh + k0, ldb);
            asm volatile("cp.async.commit_group;");
            asm volatile("cp.async.wait_group 1;");
        } else {
            asm volatile("cp.async.wait_group 0;");
        }
        __syncthreads();

        const uint32_t abase = sb + (kc & 1) * STAGE + wm * 32 * ROWB + a_lane_off;
        const uint32_t bbase = sb + (kc & 1) * STAGE + BOFF + wn * 64 * ROWB + a_lane_off;

        #pragma unroll
        for (int ks = 0; ks < 4; ++ks) {
            const uint32_t kb = ks * 32;
            uint32_t ah[2][4], al[2][4], bh[4][4];
            #pragma unroll
            for (int mt = 0; mt < 2; ++mt) {
                const uint32_t a = abase + mt * 16 * ROWB + kb;
                ldm4(ah[mt], a);
                if constexpr (NTERMS == 2) ldm4(al[mt], a + TS);
            }
            #pragma unroll
            for (int np = 0; np < 4; ++np)
                ldm4(bh[np], bbase + np * 16 * ROWB + kb);
            #pragma unroll
            for (int mt = 0; mt < 2; ++mt)
                #pragma unroll
                for (int np = 0; np < 4; ++np)
                    #pragma unroll
                    for (int h = 0; h < 2; ++h) {
                        float* c = acc[mt][np * 2 + h];
                        mma16816(c, ah[mt], bh[np][h], bh[np][h + 2]);
                        if constexpr (NTERMS == 2)
                            mma16816(c, al[mt], bh[np][h], bh[np][h + 2]);
                    }
        }
        __syncthreads();
    }
}

constexpr unsigned SMEM_A2 = 6 * TS;   // 110592 (A split)
constexpr unsigned SMEM_A1 = 4 * TS;   // 73728

// ---------------- GEMM kernels ----------------
// Projection: Y[m,n] = x[m,n] + sum_c xh[m,c]*E[n,c] + bias[n]   (E = W - I)
__global__ __launch_bounds__(256, 1)
void gemm_proj_k(const __half* __restrict__ Xh, const __half* __restrict__ Eh,
                 const float* __restrict__ x32, const float* __restrict__ bias,
                 float* __restrict__ Y) {
    extern __shared__ char smem[];
    const int m0 = blockIdx.y * 128, n0 = blockIdx.x * 128;
    float acc[2][8][4] = {};
    hmma_mainloop<1>(Xh + (size_t)m0 * kC, nullptr, Eh + (size_t)n0 * kC,
                     kC, kC, kC, smem, acc);
    const int wid = threadIdx.x >> 5, lane = threadIdx.x & 31;
    const int wm = wid >> 1, wn = wid & 1;
    #pragma unroll
    for (int mt = 0; mt < 2; ++mt)
        #pragma unroll
        for (int nt = 0; nt < 8; ++nt) {
            const int r0 = m0 + wm * 32 + mt * 16 + (lane >> 2);
            const int c  = n0 + wn * 64 + nt * 8 + (lane & 3) * 2;
            const float* a = acc[mt][nt];
            const float2 x0 = *(const float2*)(x32 + (size_t)r0 * kC + c);
            const float2 x1 = *(const float2*)(x32 + (size_t)(r0 + 8) * kC + c);
            *(float2*)(Y + (size_t)r0 * kC + c) =
                make_float2(a[0] + x0.x + bias[c], a[1] + x0.y + bias[c + 1]);
            *(float2*)(Y + (size_t)(r0 + 8) * kC + c) =
                make_float2(a[2] + x1.x + bias[c], a[3] + x1.y + bias[c + 1]);
        }
}

__global__ __launch_bounds__(256, 1)
void gemm_attn_k(const __half* __restrict__ qh, const __half* __restrict__ ql,
                 const __half* __restrict__ kh,
                 const float* __restrict__ mask, const float* __restrict__ scale_ptr,
                 float* __restrict__ P32) {
    extern __shared__ char smem[];
    const int b = blockIdx.z;
    const int m0 = blockIdx.y * 128, n0 = blockIdx.x * 128;
    const size_t aoff = ((size_t)b * kNQ + m0) * kC;
    const size_t boff = ((size_t)b * kNS + n0) * kC;
    float acc[2][8][4] = {};
    hmma_mainloop<2>(qh + aoff, ql + aoff, kh + boff, kC, kC, kC, smem, acc);
    const int wid = threadIdx.x >> 5, lane = threadIdx.x & 31;
    const int wm = wid >> 1, wn = wid & 1;
    const float sc = scale_ptr[0];
    #pragma unroll
    for (int mt = 0; mt < 2; ++mt)
        #pragma unroll
        for (int nt = 0; nt < 8; ++nt) {
            const int r0 = m0 + wm * 32 + mt * 16 + (lane >> 2);
            const int c  = n0 + wn * 64 + nt * 8 + (lane & 3) * 2;
            const float* a = acc[mt][nt];
            const float mk0 = mask[(size_t)b * kNS + c];
            const float mk1 = mask[(size_t)b * kNS + c + 1];
            const float e0 = __expf(sc * a[0] - sc - 1000.0f * mk0);
            const float e1 = __expf(sc * a[1] - sc - 1000.0f * mk1);
            const float e2 = __expf(sc * a[2] - sc - 1000.0f * mk0);
            const float e3 = __expf(sc * a[3] - sc - 1000.0f * mk1);
            const size_t rb0 = ((size_t)b * kNQ + r0) * kNS + c;
            const size_t rb1 = rb0 + (size_t)8 * kNS;
            *(float2*)(P32 + rb0) = make_float2(e0, e1);
            *(float2*)(P32 + rb1) = make_float2(e2, e3);
        }
}

__global__ __launch_bounds__(256, 1)
void gemm_pv_k(const __half* __restrict__ Ph, const __half* __restrict__ Vt,
               const float* __restrict__ idt,
               const float* __restrict__ awp, const float* __restrict__ owp,
               float* __restrict__ out) {
    extern __shared__ char smem[];
    const int m0 = blockIdx.y * 128;
    const int n0 = blockIdx.x * 128;
    const int b  = m0 / kNQ;
    float acc[2][8][4] = {};
    hmma_mainloop<1>(Ph + (size_t)m0 * kNS, nullptr,
                     Vt + ((size_t)b * kD + n0) * kNS, kNS, kNS, kNS, smem, acc);
    const int wid = threadIdx.x >> 5, lane = threadIdx.x & 31;
    const int wm = wid >> 1, wn = wid & 1;
    const float aw = awp[0], ow = owp[0];
    #pragma unroll
    for (int mt = 0; mt < 2; ++mt) {
        const int r0 = m0 + wm * 32 + mt * 16 + (lane >> 2);
        #pragma unroll
        for (int nt = 0; nt < 8; ++nt) {
            const int c = n0 + wn * 64 + nt * 8 + (lane & 3) * 2;
            const float* a = acc[mt][nt];
            const float2 d0 = *(const float2*)(idt + (size_t)r0 * kD + c);
            const float2 d1 = *(const float2*)(idt + (size_t)(r0 + 8) * kD + c);
            *(float2*)(out + (size_t)r0 * kD + c) =
                make_float2(aw * a[0] + ow * d0.x, aw * a[1] + ow * d0.y);
            *(float2*)(out + (size_t)(r0 + 8) * kD + c) =
                make_float2(aw * a[2] + ow * d1.x, aw * a[3] + ow * d1.y);
        }
    }
}

// ---------------- support kernels ----------------
__device__ __forceinline__ float block_reduce_sum(float v) {
    __shared__ float red[32];
    __shared__ float total;
    #pragma unroll
    for (int o = 16; o > 0; o >>= 1) v += __shfl_down_sync(0xffffffffu, v, o);
    const int lane = threadIdx.x & 31, w = threadIdx.x >> 5;
    if (lane == 0) red[w] = v;
    __syncthreads();
    if (w == 0) {
        v = (lane < (int)(blockDim.x >> 5)) ? red[lane] : 0.0f;
        #pragma unroll
        for (int o = 16; o > 0; o >>= 1) v += __shfl_down_sync(0xffffffffu, v, o);
        if (lane == 0) total = v;
    }
    __syncthreads();
    return total;
}

// fp32 -> fp16 (hi only)
__global__ void to_half(const float* __restrict__ x, __half* __restrict__ hi, size_t n4) {
    const size_t i = (size_t)blockIdx.x * blockDim.x + threadIdx.x;
    if (i >= n4) return;
    const float4 v = ((const float4*)x)[i];
    ((__half2*)hi)[2 * i]     = __floats2half2_rn(v.x, v.y);
    ((__half2*)hi)[2 * i + 1] = __floats2half2_rn(v.z, v.w);
}

// E = W - I (fp16)
__global__ void make_E(const float* __restrict__ W, __half* __restrict__ E) {
    const size_t i = (size_t)blockIdx.x * blockDim.x + threadIdx.x;   // float4 idx
    const size_t base = i * 4;
    if (base >= (size_t)kC * kC) return;
    float4 w = *(const float4*)(W + base);
    const int n = (int)(base / kC);
    const int c = (int)(base % kC);
    if (n == c)     w.x -= 1.0f;
    if (n == c + 1) w.y -= 1.0f;
    if (n == c + 2) w.z -= 1.0f;
    if (n == c + 3) w.w -= 1.0f;
    ((__half2*)E)[2 * i]     = __floats2half2_rn(w.x, w.y);
    ((__half2*)E)[2 * i + 1] = __floats2half2_rn(w.z, w.w);
}

// row l2norm of fp32 rows (len kC) -> fp16 hi (+ optional lo residual)
__global__ void l2norm_split(const float* __restrict__ src, __half* __restrict__ hi,
                             __half* __restrict__ lo) {
    const float* p = src + (size_t)blockIdx.x * kC;
    float ss = 0.0f;
    #pragma unroll
    for (int i = threadIdx.x * 4; i < kC; i += 1024) {
        const float4 v = *(const float4*)(p + i);
        ss += v.x * v.x + v.y * v.y + v.z * v.z + v.w * v.w;
    }
    const float tot = block_reduce_sum(ss);
    const float inv = 1.0f / fmaxf(sqrtf(tot), 1e-12f);
    __half* ho = hi + (size_t)blockIdx.x * kC;
    __half* lg = lo ? lo + (size_t)blockIdx.x * kC : nullptr;
    #pragma unroll
    for (int i = threadIdx.x * 4; i < kC; i += 1024) {
        const float4 v = *(const float4*)(p + i);
        const float x0 = v.x * inv, x1 = v.y * inv, x2 = v.z * inv, x3 = v.w * inv;
        const __half h0 = __float2half_rn(x0), h1 = __float2half_rn(x1);
        const __half h2 = __float2half_rn(x2), h3 = __float2half_rn(x3);
        *(__half2*)(ho + i)     = __halves2half2(h0, h1);
        *(__half2*)(ho + i + 2) = __halves2half2(h2, h3);
        if (lg) {
            *(__half2*)(lg + i)     = __halves2half2(__float2half_rn(x0 - __half2float(h0)),
                                                     __float2half_rn(x1 - __half2float(h1)));
            *(__half2*)(lg + i + 2) = __halves2half2(__float2half_rn(x2 - __half2float(h2)),
                                                     __float2half_rn(x3 - __half2float(h3)));
        }
    }
}

__global__ void transpose_v(const float* __restrict__ v, __half* __restrict__ vt) {
    __shared__ float t[32][33];
    const int b  = blockIdx.z;
    const int s0 = blockIdx.x * 32;
    const int d0 = blockIdx.y * 32;
    const int tx = threadIdx.x, ty = threadIdx.y;
    #pragma unroll
    for (int i = 0; i < 32; i += 8)
        t[ty + i][tx] = v[((size_t)b * kNS + s0 + ty + i) * kD + d0 + tx];
    __syncthreads();
    #pragma unroll
    for (int i = 0; i < 32; i += 8)
        vt[((size_t)b * kD + d0 + ty + i) * kNS + s0 + tx] = __float2half_rn(t[tx][ty + i]);
}

__global__ void row_sum(const float* __restrict__ P, float* __restrict__ rs) {
    const float* p = P + (size_t)blockIdx.x * kNS;
    float s = 0.0f;
    #pragma unroll
    for (int i = threadIdx.x * 4; i < kNS; i += 1024) {
        const float4 v = *(const float4*)(p + i);
        s += v.x + v.y + v.z + v.w;
    }
    const float tot = block_reduce_sum(s);
    if (threadIdx.x == 0) rs[blockIdx.x] = tot;
}

// Normalize attn in place AND emit fp16 normalized weights for PV.
__global__ void attn_norm(float* __restrict__ P, const float* __restrict__ rs,
                          __half* __restrict__ Ph) {
    const size_t e = ((size_t)blockIdx.x * blockDim.x + threadIdx.x) * 4;
    const float inv = 1.0f / rs[e / kNS];
    float4 x = *(const float4*)(P + e);
    x.x *= inv; x.y *= inv; x.z *= inv; x.w *= inv;
    *(float4*)(P + e) = x;
    *(__half2*)(Ph + e)     = __floats2half2_rn(x.x, x.y);
    *(__half2*)(Ph + e + 2) = __floats2half2_rn(x.z, x.w);
}

// ---------------- launch ----------------
extern "C" void kernel_launch(void* const* d_in, const int* in_sizes, int n_in,
                              void* d_out, int out_size) {
    (void)in_sizes; (void)n_in; (void)out_size;
    const float* k     = (const float*)d_in[0];
    const float* v     = (const float*)d_in[1];
    const float* q     = (const float*)d_in[2];
    const float* idt   = (const float*)d_in[3];
    const float* mask  = (const float*)d_in[4];
    const float* W     = (const float*)d_in[5];
    const float* bias  = (const float*)d_in[6];
    const float* scale = (const float*)d_in[7];
    const float* attwt = (const float*)d_in[8];
    const float* orgwt = (const float*)d_in[9];

    float* out  = (float*)d_out;
    float* attn = out + (size_t)kB * kNQ * kD;

    __half *ah, *al, *bh, *eh, *vt, *ph;
    float *qp, *kp, *rs;
    cudaGetSymbolAddress((void**)&ah, g_ah);
    cudaGetSymbolAddress((void**)&al, g_al);
    cudaGetSymbolAddress((void**)&bh, g_bh);
    cudaGetSymbolAddress((void**)&eh, g_eh);
    cudaGetSymbolAddress((void**)&vt, g_vt);
    cudaGetSymbolAddress((void**)&ph, g_ph);
    cudaGetSymbolAddress((void**)&qp, g_qp);
    cudaGetSymbolAddress((void**)&kp, g_kp);
    cudaGetSymbolAddress((void**)&rs, g_rowsum);

    static bool attr_done = false;
    if (!attr_done) {
        cudaFuncSetAttribute(gemm_proj_k, cudaFuncAttributeMaxDynamicSharedMemorySize, SMEM_A1);
        cudaFuncSetAttribute(gemm_attn_k, cudaFuncAttributeMaxDynamicSharedMemorySize, SMEM_A2);
        cudaFuncSetAttribute(gemm_pv_k,   cudaFuncAttributeMaxDynamicSharedMemorySize, SMEM_A1);
        attr_done = true;
    }

    const size_t nq4 = (size_t)kMQ * kC / 4;
    to_half<<<(unsigned)((nq4 + 255) / 256), 256>>>(q, ah, nq4);
    to_half<<<(unsigned)((nq4 + 255) / 256), 256>>>(k, bh, nq4);
    const size_t nw4 = (size_t)kC * kC / 4;
    make_E<<<(unsigned)((nw4 + 255) / 256), 256>>>(W, eh);
    transpose_v<<<dim3(kNS / 32, kD / 32, kB), dim3(32, 8)>>>(v, vt);

    gemm_proj_k<<<dim3(kC / 128, kMQ / 128), 256, SMEM_A1>>>(ah, eh, q, bias, qp);
    gemm_proj_k<<<dim3(kC / 128, kMK / 128), 256, SMEM_A1>>>(bh, eh, k, bias, kp);

    l2norm_split<<<kMQ, 256>>>(qp, ah, al);       // qp -> hi + lo
    l2norm_split<<<kMK, 256>>>(kp, bh, nullptr);  // kp -> hi only

    gemm_attn_k<<<dim3(kNS / 128, kNQ / 128, kB), 256, SMEM_A2>>>(ah, al, bh,
                                                                  mask, scale, attn);
    row_sum<<<kMQ, 256>>>(attn, rs);

    const size_t nvec4 = (size_t)kB * kNQ * kNS / 4;
    attn_norm<<<(unsigned)(nvec4 / 256), 256>>>(attn, rs, ph);

    gemm_pv_k<<<dim3(kD / 128, kMQ / 128), 256, SMEM_A1>>>(ph, vt, idt, attwt, orgwt, out);
}

// round 8
// speedup vs baseline: 7.1103x; 1.5542x over previous
#include <cuda_runtime.h>
#include <cuda_fp16.h>
#include <math.h>
#include <stdint.h>

constexpr int kB  = 8;
constexpr int kNQ = 4096;
constexpr int kNS = 4096;
constexpr int kC  = 2048;
constexpr int kD  = 512;
constexpr int kMQ = kB * kNQ;   // 32768
constexpr int kMK = kB * kNS;   // 32768

// Scratch (__device__ globals; allocation-free rule)
__device__ __half g_ah[(size_t)kMQ * kC];        // q hi -> later qp hi
__device__ __half g_bh[(size_t)kMK * kC];        // k hi -> later kp hi
__device__ __half g_eh[(size_t)kC * kC];         // E = W - I, fp16
__device__ __half g_vt[(size_t)kB * kD * kNS];   // v transposed [b, d, s] fp16
__device__ __half g_ph[(size_t)kMQ * kNS];       // NORMALIZED attn weights fp16
__device__ float  g_qp[(size_t)kMQ * kC];
__device__ float  g_kp[(size_t)kMK * kC];
__device__ float  g_part[(size_t)kMQ * 32];      // per-(row, col-block) partial sums
__device__ float  g_rowsum[kMQ];

// ---------------- helpers ----------------
__device__ __forceinline__ uint32_t smem_u32(const void* p) {
    uint32_t a;
    asm("{ .reg .u64 t; cvta.to.shared.u64 t, %1; cvt.u32.u64 %0, t; }" : "=r"(a) : "l"(p));
    return a;
}
__device__ __forceinline__ void ldm4(uint32_t r[4], uint32_t addr) {
    asm volatile("ldmatrix.sync.aligned.m8n8.x4.shared.b16 {%0,%1,%2,%3}, [%4];"
                 : "=r"(r[0]), "=r"(r[1]), "=r"(r[2]), "=r"(r[3]) : "r"(addr));
}
__device__ __forceinline__ void mma16816(float c[4], const uint32_t a[4],
                                         uint32_t b0, uint32_t b1) {
    asm volatile(
        "mma.sync.aligned.m16n8k16.row.col.f32.f16.f16.f32 "
        "{%0,%1,%2,%3}, {%4,%5,%6,%7}, {%8,%9}, {%0,%1,%2,%3};"
        : "+f"(c[0]), "+f"(c[1]), "+f"(c[2]), "+f"(c[3])
        : "r"(a[0]), "r"(a[1]), "r"(a[2]), "r"(a[3]), "r"(b0), "r"(b1));
}

// Tile geometry: block 128x128, BK=64 fp16, rows padded to 144 B (conflict-free)
constexpr int BK = 64;
constexpr uint32_t ROWB = 144;
constexpr uint32_t TS   = 128 * ROWB;          // 18432 B per tile
constexpr unsigned SMEM_GM = 4 * TS;           // 73728: 2 stages x (A + B)

// Load a 128 x 64 (fp16) K-major tile into padded SMEM via cp.async (16B chunks)
__device__ __forceinline__ void load_tile(uint32_t dst, const __half* src, int ldk) {
    const int tid = threadIdx.x;
    #pragma unroll
    for (int i = 0; i < 4; ++i) {
        const int idx = tid + i * 256;      // 1024 chunks: 128 rows x 8 segs
        const int row = idx >> 3;
        const int seg = idx & 7;
        asm volatile("cp.async.cg.shared.global [%0], [%1], 16;"
                     :: "r"(dst + row * ROWB + seg * 16),
                        "l"(src + (size_t)row * ldk + seg * 8) : "memory");
    }
}

// ---------------------------------------------------------------------------
// HMMA mainloop: acc[2][8][4] accumulates C[128][128] = A * B^T.
// 8 warps as 4(m) x 2(n); warp tile 32x64. Double-buffered cp.async.
// ---------------------------------------------------------------------------
__device__ __forceinline__ void hmma_mainloop(
    const __half* A, const __half* B, int lda, int ldb, int K,
    char* smem, float acc[2][8][4])
{
    const int tid  = threadIdx.x;
    const int wid  = tid >> 5;
    const int lane = tid & 31;
    const int wm   = wid >> 1;
    const int wn   = wid & 1;
    constexpr uint32_t STAGE = 2 * TS;
    const uint32_t sb = smem_u32(smem);
    const int NK = K / BK;

    load_tile(sb, A, lda);
    load_tile(sb + TS, B, ldb);
    asm volatile("cp.async.commit_group;");

    const uint32_t lane_off = (uint32_t)((lane & 15) * ROWB + ((lane >> 4) * 8) * 2);

    for (int kc = 0; kc < NK; ++kc) {
        if (kc + 1 < NK) {
            const uint32_t s = sb + ((kc + 1) & 1) * STAGE;
            const size_t k0 = (size_t)(kc + 1) * BK;
            load_tile(s, A + k0, lda);
            load_tile(s + TS, B + k0, ldb);
            asm volatile("cp.async.commit_group;");
            asm volatile("cp.async.wait_group 1;");
        } else {
            asm volatile("cp.async.wait_group 0;");
        }
        __syncthreads();

        const uint32_t abase = sb + (kc & 1) * STAGE + wm * 32 * ROWB + lane_off;
        const uint32_t bbase = sb + (kc & 1) * STAGE + TS + wn * 64 * ROWB + lane_off;

        #pragma unroll
        for (int ks = 0; ks < 4; ++ks) {
            const uint32_t kb = ks * 32;
            uint32_t ah[2][4], bh[4][4];
            #pragma unroll
            for (int mt = 0; mt < 2; ++mt)
                ldm4(ah[mt], abase + mt * 16 * ROWB + kb);
            #pragma unroll
            for (int np = 0; np < 4; ++np)
                ldm4(bh[np], bbase + np * 16 * ROWB + kb);
            #pragma unroll
            for (int mt = 0; mt < 2; ++mt)
                #pragma unroll
                for (int np = 0; np < 4; ++np)
                    #pragma unroll
                    for (int h = 0; h < 2; ++h)
                        mma16816(acc[mt][np * 2 + h], ah[mt], bh[np][h], bh[np][h + 2]);
        }
        __syncthreads();
    }
}

// ---------------- GEMM kernels ----------------
// Projection: Y[m,n] = x[m,n] + sum_c xh[m,c]*E[n,c] + bias[n]   (E = W - I)
__global__ __launch_bounds__(256, 2)
void gemm_proj_k(const __half* __restrict__ Xh, const __half* __restrict__ Eh,
                 const float* __restrict__ x32, const float* __restrict__ bias,
                 float* __restrict__ Y) {
    extern __shared__ char smem[];
    const int m0 = blockIdx.y * 128, n0 = blockIdx.x * 128;
    float acc[2][8][4] = {};
    hmma_mainloop(Xh + (size_t)m0 * kC, Eh + (size_t)n0 * kC, kC, kC, kC, smem, acc);
    const int wid = threadIdx.x >> 5, lane = threadIdx.x & 31;
    const int wm = wid >> 1, wn = wid & 1;
    #pragma unroll
    for (int mt = 0; mt < 2; ++mt)
        #pragma unroll
        for (int nt = 0; nt < 8; ++nt) {
            const int r0 = m0 + wm * 32 + mt * 16 + (lane >> 2);
            const int c  = n0 + wn * 64 + nt * 8 + (lane & 3) * 2;
            const float* a = acc[mt][nt];
            const float2 x0 = *(const float2*)(x32 + (size_t)r0 * kC + c);
            const float2 x1 = *(const float2*)(x32 + (size_t)(r0 + 8) * kC + c);
            *(float2*)(Y + (size_t)r0 * kC + c) =
                make_float2(a[0] + x0.x + bias[c], a[1] + x0.y + bias[c + 1]);
            *(float2*)(Y + (size_t)(r0 + 8) * kC + c) =
                make_float2(a[2] + x1.x + bias[c], a[3] + x1.y + bias[c + 1]);
        }
}

// QK^T + exp epilogue + deterministic per-block partial row sums
__global__ __launch_bounds__(256, 2)
void gemm_attn_k(const __half* __restrict__ qh, const __half* __restrict__ kh,
                 const float* __restrict__ mask, const float* __restrict__ scale_ptr,
                 float* __restrict__ P32, float* __restrict__ part) {
    extern __shared__ char smem[];
    const int b = blockIdx.z;
    const int m0 = blockIdx.y * 128, n0 = blockIdx.x * 128;
    const size_t aoff = ((size_t)b * kNQ + m0) * kC;
    const size_t boff = ((size_t)b * kNS + n0) * kC;
    float acc[2][8][4] = {};
    hmma_mainloop(qh + aoff, kh + boff, kC, kC, kC, smem, acc);
    const int wid = threadIdx.x >> 5, lane = threadIdx.x & 31;
    const int wm = wid >> 1, wn = wid & 1;
    const float sc = scale_ptr[0];
    float srow[2][2] = {};
    #pragma unroll
    for (int mt = 0; mt < 2; ++mt)
        #pragma unroll
        for (int nt = 0; nt < 8; ++nt) {
            const int r0 = m0 + wm * 32 + mt * 16 + (lane >> 2);
            const int c  = n0 + wn * 64 + nt * 8 + (lane & 3) * 2;
            const float* a = acc[mt][nt];
            const float mk0 = mask[(size_t)b * kNS + c];
            const float mk1 = mask[(size_t)b * kNS + c + 1];
            const float e0 = __expf(sc * a[0] - sc - 1000.0f * mk0);
            const float e1 = __expf(sc * a[1] - sc - 1000.0f * mk1);
            const float e2 = __expf(sc * a[2] - sc - 1000.0f * mk0);
            const float e3 = __expf(sc * a[3] - sc - 1000.0f * mk1);
            const size_t rb0 = ((size_t)b * kNQ + r0) * kNS + c;
            const size_t rb1 = rb0 + (size_t)8 * kNS;
            *(float2*)(P32 + rb0) = make_float2(e0, e1);
            *(float2*)(P32 + rb1) = make_float2(e2, e3);
            srow[mt][0] += e0 + e1;
            srow[mt][1] += e2 + e3;
        }
    // deterministic block-level row sums: quad shuffle -> smem -> combine halves
    float* psum = (float*)smem;   // [128][2]
    #pragma unroll
    for (int mt = 0; mt < 2; ++mt)
        #pragma unroll
        for (int h = 0; h < 2; ++h) {
            float s = srow[mt][h];
            s += __shfl_down_sync(0xffffffffu, s, 1);
            s += __shfl_down_sync(0xffffffffu, s, 2);
            if ((lane & 3) == 0)
                psum[(wm * 32 + mt * 16 + (lane >> 2) + h * 8) * 2 + wn] = s;
        }
    __syncthreads();
    if (threadIdx.x < 128)
        part[((size_t)b * kNQ + m0 + threadIdx.x) * 32 + blockIdx.x] =
            psum[threadIdx.x * 2] + psum[threadIdx.x * 2 + 1];
}

__global__ __launch_bounds__(256, 2)
void gemm_pv_k(const __half* __restrict__ Ph, const __half* __restrict__ Vt,
               const float* __restrict__ idt,
               const float* __restrict__ awp, const float* __restrict__ owp,
               float* __restrict__ out) {
    extern __shared__ char smem[];
    const int m0 = blockIdx.y * 128;
    const int n0 = blockIdx.x * 128;
    const int b  = m0 / kNQ;
    float acc[2][8][4] = {};
    hmma_mainloop(Ph + (size_t)m0 * kNS, Vt + ((size_t)b * kD + n0) * kNS,
                  kNS, kNS, kNS, smem, acc);
    const int wid = threadIdx.x >> 5, lane = threadIdx.x & 31;
    const int wm = wid >> 1, wn = wid & 1;
    const float aw = awp[0], ow = owp[0];
    #pragma unroll
    for (int mt = 0; mt < 2; ++mt) {
        const int r0 = m0 + wm * 32 + mt * 16 + (lane >> 2);
        #pragma unroll
        for (int nt = 0; nt < 8; ++nt) {
            const int c = n0 + wn * 64 + nt * 8 + (lane & 3) * 2;
            const float* a = acc[mt][nt];
            const float2 d0 = *(const float2*)(idt + (size_t)r0 * kD + c);
            const float2 d1 = *(const float2*)(idt + (size_t)(r0 + 8) * kD + c);
            *(float2*)(out + (size_t)r0 * kD + c) =
                make_float2(aw * a[0] + ow * d0.x, aw * a[1] + ow * d0.y);
            *(float2*)(out + (size_t)(r0 + 8) * kD + c) =
                make_float2(aw * a[2] + ow * d1.x, aw * a[3] + ow * d1.y);
        }
    }
}

// ---------------- support kernels ----------------
__device__ __forceinline__ float block_reduce_sum(float v) {
    __shared__ float red[32];
    __shared__ float total;
    #pragma unroll
    for (int o = 16; o > 0; o >>= 1) v += __shfl_down_sync(0xffffffffu, v, o);
    const int lane = threadIdx.x & 31, w = threadIdx.x >> 5;
    if (lane == 0) red[w] = v;
    __syncthreads();
    if (w == 0) {
        v = (lane < (int)(blockDim.x >> 5)) ? red[lane] : 0.0f;
        #pragma unroll
        for (int o = 16; o > 0; o >>= 1) v += __shfl_down_sync(0xffffffffu, v, o);
        if (lane == 0) total = v;
    }
    __syncthreads();
    return total;
}

__global__ void to_half(const float* __restrict__ x, __half* __restrict__ hi, size_t n4) {
    const size_t i = (size_t)blockIdx.x * blockDim.x + threadIdx.x;
    if (i >= n4) return;
    const float4 v = ((const float4*)x)[i];
    ((__half2*)hi)[2 * i]     = __floats2half2_rn(v.x, v.y);
    ((__half2*)hi)[2 * i + 1] = __floats2half2_rn(v.z, v.w);
}

__global__ void make_E(const float* __restrict__ W, __half* __restrict__ E) {
    const size_t i = (size_t)blockIdx.x * blockDim.x + threadIdx.x;   // float4 idx
    const size_t base = i * 4;
    if (base >= (size_t)kC * kC) return;
    float4 w = *(const float4*)(W + base);
    const int n = (int)(base / kC);
    const int c = (int)(base % kC);
    if (n == c)     w.x -= 1.0f;
    if (n == c + 1) w.y -= 1.0f;
    if (n == c + 2) w.z -= 1.0f;
    if (n == c + 3) w.w -= 1.0f;
    ((__half2*)E)[2 * i]     = __floats2half2_rn(w.x, w.y);
    ((__half2*)E)[2 * i + 1] = __floats2half2_rn(w.z, w.w);
}

// row l2norm of fp32 rows (len kC) -> fp16
__global__ void l2norm_h(const float* __restrict__ src, __half* __restrict__ hi) {
    const float* p = src + (size_t)blockIdx.x * kC;
    float ss = 0.0f;
    #pragma unroll
    for (int i = threadIdx.x * 4; i < kC; i += 1024) {
        const float4 v = *(const float4*)(p + i);
        ss += v.x * v.x + v.y * v.y + v.z * v.z + v.w * v.w;
    }
    const float tot = block_reduce_sum(ss);
    const float inv = 1.0f / fmaxf(sqrtf(tot), 1e-12f);
    __half* ho = hi + (size_t)blockIdx.x * kC;
    #pragma unroll
    for (int i = threadIdx.x * 4; i < kC; i += 1024) {
        const float4 v = *(const float4*)(p + i);
        *(__half2*)(ho + i)     = __floats2half2_rn(v.x * inv, v.y * inv);
        *(__half2*)(ho + i + 2) = __floats2half2_rn(v.z * inv, v.w * inv);
    }
}

__global__ void transpose_v(const float* __restrict__ v, __half* __restrict__ vt) {
    __shared__ float t[32][33];
    const int b  = blockIdx.z;
    const int s0 = blockIdx.x * 32;
    const int d0 = blockIdx.y * 32;
    const int tx = threadIdx.x, ty = threadIdx.y;
    #pragma unroll
    for (int i = 0; i < 32; i += 8)
        t[ty + i][tx] = v[((size_t)b * kNS + s0 + ty + i) * kD + d0 + tx];
    __syncthreads();
    #pragma unroll
    for (int i = 0; i < 32; i += 8)
        vt[((size_t)b * kD + d0 + ty + i) * kNS + s0 + tx] = __float2half_rn(t[tx][ty + i]);
}

// reduce 32 per-block partials per row -> rowsum (deterministic fixed order)
__global__ void rowsum_reduce(const float* __restrict__ part, float* __restrict__ rs) {
    const int r = blockIdx.x * 256 + threadIdx.x;
    const float* p = part + (size_t)r * 32;
    float s = 0.0f;
    #pragma unroll
    for (int j = 0; j < 32; ++j) s += p[j];
    rs[r] = s;
}

// Normalize attn in place AND emit fp16 normalized weights for PV.
__global__ void attn_norm(float* __restrict__ P, const float* __restrict__ rs,
                          __half* __restrict__ Ph) {
    const size_t e = ((size_t)blockIdx.x * blockDim.x + threadIdx.x) * 4;
    const float inv = 1.0f / rs[e / kNS];
    float4 x = *(const float4*)(P + e);
    x.x *= inv; x.y *= inv; x.z *= inv; x.w *= inv;
    *(float4*)(P + e) = x;
    *(__half2*)(Ph + e)     = __floats2half2_rn(x.x, x.y);
    *(__half2*)(Ph + e + 2) = __floats2half2_rn(x.z, x.w);
}

// ---------------- launch ----------------
extern "C" void kernel_launch(void* const* d_in, const int* in_sizes, int n_in,
                              void* d_out, int out_size) {
    (void)in_sizes; (void)n_in; (void)out_size;
    const float* k     = (const float*)d_in[0];
    const float* v     = (const float*)d_in[1];
    const float* q     = (const float*)d_in[2];
    const float* idt   = (const float*)d_in[3];
    const float* mask  = (const float*)d_in[4];
    const float* W     = (const float*)d_in[5];
    const float* bias  = (const float*)d_in[6];
    const float* scale = (const float*)d_in[7];
    const float* attwt = (const float*)d_in[8];
    const float* orgwt = (const float*)d_in[9];

    float* out  = (float*)d_out;
    float* attn = out + (size_t)kB * kNQ * kD;

    __half *ah, *bh, *eh, *vt, *ph;
    float *qp, *kp, *rs, *part;
    cudaGetSymbolAddress((void**)&ah, g_ah);
    cudaGetSymbolAddress((void**)&bh, g_bh);
    cudaGetSymbolAddress((void**)&eh, g_eh);
    cudaGetSymbolAddress((void**)&vt, g_vt);
    cudaGetSymbolAddress((void**)&ph, g_ph);
    cudaGetSymbolAddress((void**)&qp, g_qp);
    cudaGetSymbolAddress((void**)&kp, g_kp);
    cudaGetSymbolAddress((void**)&rs, g_rowsum);
    cudaGetSymbolAddress((void**)&part, g_part);

    static bool attr_done = false;
    if (!attr_done) {
        cudaFuncSetAttribute(gemm_proj_k, cudaFuncAttributeMaxDynamicSharedMemorySize, SMEM_GM);
        cudaFuncSetAttribute(gemm_attn_k, cudaFuncAttributeMaxDynamicSharedMemorySize, SMEM_GM);
        cudaFuncSetAttribute(gemm_pv_k,   cudaFuncAttributeMaxDynamicSharedMemorySize, SMEM_GM);
        attr_done = true;
    }

    const size_t nq4 = (size_t)kMQ * kC / 4;
    to_half<<<(unsigned)((nq4 + 255) / 256), 256>>>(q, ah, nq4);
    to_half<<<(unsigned)((nq4 + 255) / 256), 256>>>(k, bh, nq4);
    const size_t nw4 = (size_t)kC * kC / 4;
    make_E<<<(unsigned)((nw4 + 255) / 256), 256>>>(W, eh);
    transpose_v<<<dim3(kNS / 32, kD / 32, kB), dim3(32, 8)>>>(v, vt);

    gemm_proj_k<<<dim3(kC / 128, kMQ / 128), 256, SMEM_GM>>>(ah, eh, q, bias, qp);
    gemm_proj_k<<<dim3(kC / 128, kMK / 128), 256, SMEM_GM>>>(bh, eh, k, bias, kp);

    l2norm_h<<<kMQ, 256>>>(qp, ah);
    l2norm_h<<<kMK, 256>>>(kp, bh);

    gemm_attn_k<<<dim3(kNS / 128, kNQ / 128, kB), 256, SMEM_GM>>>(ah, bh, mask, scale,
                                                                  attn, part);
    rowsum_reduce<<<kMQ / 256, 256>>>(part, rs);

    const size_t nvec4 = (size_t)kB * kNQ * kNS / 4;
    attn_norm<<<(unsigned)(nvec4 / 256), 256>>>(attn, rs, ph);

    gemm_pv_k<<<dim3(kD / 128, kMQ / 128), 256, SMEM_GM>>>(ph, vt, idt, attwt, orgwt, out);
}

// round 9
// speedup vs baseline: 7.1174x; 1.0010x over previous
#include <cuda_runtime.h>
#include <cuda_fp16.h>
#include <math.h>
#include <stdint.h>

constexpr int kB  = 8;
constexpr int kNQ = 4096;
constexpr int kNS = 4096;
constexpr int kC  = 2048;
constexpr int kD  = 512;
constexpr int kMQ = kB * kNQ;   // 32768
constexpr int kMK = kB * kNS;   // 32768

// Scratch (__device__ globals; allocation-free rule)
__device__ __half g_ah[(size_t)kMQ * kC];        // q hi -> later qp hi
__device__ __half g_bh[(size_t)kMK * kC];        // k hi -> later kp hi
__device__ __half g_eh[(size_t)kC * kC];         // E = W - I, fp16
__device__ __half g_vt[(size_t)kB * kD * kNS];   // v transposed [b, d, s] fp16
__device__ __half g_ph[(size_t)kMQ * kNS];       // NORMALIZED attn weights fp16
__device__ float  g_qp[(size_t)kMQ * kC];
__device__ float  g_kp[(size_t)kMK * kC];
__device__ float  g_part[(size_t)kMQ * 32];      // per-(row, col-block) partial sums
__device__ float  g_rowsum[kMQ];

// ---------------- helpers ----------------
__device__ __forceinline__ uint32_t smem_u32(const void* p) {
    uint32_t a;
    asm("{ .reg .u64 t; cvta.to.shared.u64 t, %1; cvt.u32.u64 %0, t; }" : "=r"(a) : "l"(p));
    return a;
}
__device__ __forceinline__ void ldm4(uint32_t r[4], uint32_t addr) {
    asm volatile("ldmatrix.sync.aligned.m8n8.x4.shared.b16 {%0,%1,%2,%3}, [%4];"
                 : "=r"(r[0]), "=r"(r[1]), "=r"(r[2]), "=r"(r[3]) : "r"(addr));
}
__device__ __forceinline__ void mma16816(float c[4], const uint32_t a[4],
                                         uint32_t b0, uint32_t b1) {
    asm volatile(
        "mma.sync.aligned.m16n8k16.row.col.f32.f16.f16.f32 "
        "{%0,%1,%2,%3}, {%4,%5,%6,%7}, {%8,%9}, {%0,%1,%2,%3};"
        : "+f"(c[0]), "+f"(c[1]), "+f"(c[2]), "+f"(c[3])
        : "r"(a[0]), "r"(a[1]), "r"(a[2]), "r"(a[3]), "r"(b0), "r"(b1));
}

// Tile geometry: block 128x128, BK=64 fp16, rows padded to 144 B (conflict-free)
constexpr int BK = 64;
constexpr uint32_t ROWB = 144;
constexpr uint32_t TS   = 128 * ROWB;          // 18432 B per tile
constexpr unsigned SMEM_GM = 4 * TS;           // 73728: 2 stages x (A + B)

// Load a 128 x 64 (fp16) K-major tile into padded SMEM via cp.async (16B chunks)
__device__ __forceinline__ void load_tile(uint32_t dst, const __half* src, int ldk) {
    const int tid = threadIdx.x;
    #pragma unroll
    for (int i = 0; i < 4; ++i) {
        const int idx = tid + i * 256;      // 1024 chunks: 128 rows x 8 segs
        const int row = idx >> 3;
        const int seg = idx & 7;
        asm volatile("cp.async.cg.shared.global [%0], [%1], 16;"
                     :: "r"(dst + row * ROWB + seg * 16),
                        "l"(src + (size_t)row * ldk + seg * 8) : "memory");
    }
}

// ---------------------------------------------------------------------------
// HMMA mainloop: acc[2][8][4] accumulates C[128][128] = A * B^T.
// 8 warps as 4(m) x 2(n); warp tile 32x64. Double-buffered cp.async.
// ---------------------------------------------------------------------------
__device__ __forceinline__ void hmma_mainloop(
    const __half* A, const __half* B, int lda, int ldb, int K,
    char* smem, float acc[2][8][4])
{
    const int tid  = threadIdx.x;
    const int wid  = tid >> 5;
    const int lane = tid & 31;
    const int wm   = wid >> 1;
    const int wn   = wid & 1;
    constexpr uint32_t STAGE = 2 * TS;
    const uint32_t sb = smem_u32(smem);
    const int NK = K / BK;

    load_tile(sb, A, lda);
    load_tile(sb + TS, B, ldb);
    asm volatile("cp.async.commit_group;");

    const uint32_t lane_off = (uint32_t)((lane & 15) * ROWB + ((lane >> 4) * 8) * 2);

    for (int kc = 0; kc < NK; ++kc) {
        if (kc + 1 < NK) {
            const uint32_t s = sb + ((kc + 1) & 1) * STAGE;
            const size_t k0 = (size_t)(kc + 1) * BK;
            load_tile(s, A + k0, lda);
            load_tile(s + TS, B + k0, ldb);
            asm volatile("cp.async.commit_group;");
            asm volatile("cp.async.wait_group 1;");
        } else {
            asm volatile("cp.async.wait_group 0;");
        }
        __syncthreads();

        const uint32_t abase = sb + (kc & 1) * STAGE + wm * 32 * ROWB + lane_off;
        const uint32_t bbase = sb + (kc & 1) * STAGE + TS + wn * 64 * ROWB + lane_off;

        #pragma unroll
        for (int ks = 0; ks < 4; ++ks) {
            const uint32_t kb = ks * 32;
            uint32_t ah[2][4], bh[4][4];
            #pragma unroll
            for (int mt = 0; mt < 2; ++mt)
                ldm4(ah[mt], abase + mt * 16 * ROWB + kb);
            #pragma unroll
            for (int np = 0; np < 4; ++np)
                ldm4(bh[np], bbase + np * 16 * ROWB + kb);
            #pragma unroll
            for (int mt = 0; mt < 2; ++mt)
                #pragma unroll
                for (int np = 0; np < 4; ++np)
                    #pragma unroll
                    for (int h = 0; h < 2; ++h)
                        mma16816(acc[mt][np * 2 + h], ah[mt], bh[np][h], bh[np][h + 2]);
        }
        __syncthreads();
    }
}

// ---------------- GEMM kernels ----------------
// Projection: Y[m,n] = x[m,n] + sum_c xh[m,c]*E[n,c] + bias[n]   (E = W - I)
__global__ __launch_bounds__(256, 2)
void gemm_proj_k(const __half* __restrict__ Xh, const __half* __restrict__ Eh,
                 const float* __restrict__ x32, const float* __restrict__ bias,
                 float* __restrict__ Y) {
    extern __shared__ char smem[];
    const int m0 = blockIdx.y * 128, n0 = blockIdx.x * 128;
    float acc[2][8][4] = {};
    hmma_mainloop(Xh + (size_t)m0 * kC, Eh + (size_t)n0 * kC, kC, kC, kC, smem, acc);
    const int wid = threadIdx.x >> 5, lane = threadIdx.x & 31;
    const int wm = wid >> 1, wn = wid & 1;
    #pragma unroll
    for (int mt = 0; mt < 2; ++mt)
        #pragma unroll
        for (int nt = 0; nt < 8; ++nt) {
            const int r0 = m0 + wm * 32 + mt * 16 + (lane >> 2);
            const int c  = n0 + wn * 64 + nt * 8 + (lane & 3) * 2;
            const float* a = acc[mt][nt];
            const float2 x0 = *(const float2*)(x32 + (size_t)r0 * kC + c);
            const float2 x1 = *(const float2*)(x32 + (size_t)(r0 + 8) * kC + c);
            *(float2*)(Y + (size_t)r0 * kC + c) =
                make_float2(a[0] + x0.x + bias[c], a[1] + x0.y + bias[c + 1]);
            *(float2*)(Y + (size_t)(r0 + 8) * kC + c) =
                make_float2(a[2] + x1.x + bias[c], a[3] + x1.y + bias[c + 1]);
        }
}

// QK^T + exp epilogue + deterministic per-block partial row sums
__global__ __launch_bounds__(256, 2)
void gemm_attn_k(const __half* __restrict__ qh, const __half* __restrict__ kh,
                 const float* __restrict__ mask, const float* __restrict__ scale_ptr,
                 float* __restrict__ P32, float* __restrict__ part) {
    extern __shared__ char smem[];
    const int b = blockIdx.z;
    const int m0 = blockIdx.y * 128, n0 = blockIdx.x * 128;
    const size_t aoff = ((size_t)b * kNQ + m0) * kC;
    const size_t boff = ((size_t)b * kNS + n0) * kC;
    float acc[2][8][4] = {};
    hmma_mainloop(qh + aoff, kh + boff, kC, kC, kC, smem, acc);
    const int wid = threadIdx.x >> 5, lane = threadIdx.x & 31;
    const int wm = wid >> 1, wn = wid & 1;
    const float sc = scale_ptr[0];
    float srow[2][2] = {};
    #pragma unroll
    for (int mt = 0; mt < 2; ++mt)
        #pragma unroll
        for (int nt = 0; nt < 8; ++nt) {
            const int r0 = m0 + wm * 32 + mt * 16 + (lane >> 2);
            const int c  = n0 + wn * 64 + nt * 8 + (lane & 3) * 2;
            const float* a = acc[mt][nt];
            const float mk0 = mask[(size_t)b * kNS + c];
            const float mk1 = mask[(size_t)b * kNS + c + 1];
            const float e0 = __expf(sc * a[0] - sc - 1000.0f * mk0);
            const float e1 = __expf(sc * a[1] - sc - 1000.0f * mk1);
            const float e2 = __expf(sc * a[2] - sc - 1000.0f * mk0);
            const float e3 = __expf(sc * a[3] - sc - 1000.0f * mk1);
            const size_t rb0 = ((size_t)b * kNQ + r0) * kNS + c;
            const size_t rb1 = rb0 + (size_t)8 * kNS;
            *(float2*)(P32 + rb0) = make_float2(e0, e1);
            *(float2*)(P32 + rb1) = make_float2(e2, e3);
            srow[mt][0] += e0 + e1;
            srow[mt][1] += e2 + e3;
        }
    // deterministic block-level row sums: quad shuffle -> smem -> combine halves
    float* psum = (float*)smem;   // [128][2]
    #pragma unroll
    for (int mt = 0; mt < 2; ++mt)
        #pragma unroll
        for (int h = 0; h < 2; ++h) {
            float s = srow[mt][h];
            s += __shfl_down_sync(0xffffffffu, s, 1);
            s += __shfl_down_sync(0xffffffffu, s, 2);
            if ((lane & 3) == 0)
                psum[(wm * 32 + mt * 16 + (lane >> 2) + h * 8) * 2 + wn] = s;
        }
    __syncthreads();
    if (threadIdx.x < 128)
        part[((size_t)b * kNQ + m0 + threadIdx.x) * 32 + blockIdx.x] =
            psum[threadIdx.x * 2] + psum[threadIdx.x * 2 + 1];
}

__global__ __launch_bounds__(256, 2)
void gemm_pv_k(const __half* __restrict__ Ph, const __half* __restrict__ Vt,
               const float* __restrict__ idt,
               const float* __restrict__ awp, const float* __restrict__ owp,
               float* __restrict__ out) {
    extern __shared__ char smem[];
    const int m0 = blockIdx.y * 128;
    const int n0 = blockIdx.x * 128;
    const int b  = m0 / kNQ;
    float acc[2][8][4] = {};
    hmma_mainloop(Ph + (size_t)m0 * kNS, Vt + ((size_t)b * kD + n0) * kNS,
                  kNS, kNS, kNS, smem, acc);
    const int wid = threadIdx.x >> 5, lane = threadIdx.x & 31;
    const int wm = wid >> 1, wn = wid & 1;
    const float aw = awp[0], ow = owp[0];
    #pragma unroll
    for (int mt = 0; mt < 2; ++mt) {
        const int r0 = m0 + wm * 32 + mt * 16 + (lane >> 2);
        #pragma unroll
        for (int nt = 0; nt < 8; ++nt) {
            const int c = n0 + wn * 64 + nt * 8 + (lane & 3) * 2;
            const float* a = acc[mt][nt];
            const float2 d0 = *(const float2*)(idt + (size_t)r0 * kD + c);
            const float2 d1 = *(const float2*)(idt + (size_t)(r0 + 8) * kD + c);
            *(float2*)(out + (size_t)r0 * kD + c) =
                make_float2(aw * a[0] + ow * d0.x, aw * a[1] + ow * d0.y);
            *(float2*)(out + (size_t)(r0 + 8) * kD + c) =
                make_float2(aw * a[2] + ow * d1.x, aw * a[3] + ow * d1.y);
        }
    }
}

// ---------------- support kernels ----------------
__device__ __forceinline__ float block_reduce_sum(float v) {
    __shared__ float red[32];
    __shared__ float total;
    #pragma unroll
    for (int o = 16; o > 0; o >>= 1) v += __shfl_down_sync(0xffffffffu, v, o);
    const int lane = threadIdx.x & 31, w = threadIdx.x >> 5;
    if (lane == 0) red[w] = v;
    __syncthreads();
    if (w == 0) {
        v = (lane < (int)(blockDim.x >> 5)) ? red[lane] : 0.0f;
        #pragma unroll
        for (int o = 16; o > 0; o >>= 1) v += __shfl_down_sync(0xffffffffu, v, o);
        if (lane == 0) total = v;
    }
    __syncthreads();
    return total;
}

__global__ void to_half(const float* __restrict__ x, __half* __restrict__ hi, size_t n4) {
    const size_t i = (size_t)blockIdx.x * blockDim.x + threadIdx.x;
    if (i >= n4) return;
    const float4 v = ((const float4*)x)[i];
    ((__half2*)hi)[2 * i]     = __floats2half2_rn(v.x, v.y);
    ((__half2*)hi)[2 * i + 1] = __floats2half2_rn(v.z, v.w);
}

__global__ void make_E(const float* __restrict__ W, __half* __restrict__ E) {
    const size_t i = (size_t)blockIdx.x * blockDim.x + threadIdx.x;   // float4 idx
    const size_t base = i * 4;
    if (base >= (size_t)kC * kC) return;
    float4 w = *(const float4*)(W + base);
    const int n = (int)(base / kC);
    const int c = (int)(base % kC);
    if (n == c)     w.x -= 1.0f;
    if (n == c + 1) w.y -= 1.0f;
    if (n == c + 2) w.z -= 1.0f;
    if (n == c + 3) w.w -= 1.0f;
    ((__half2*)E)[2 * i]     = __floats2half2_rn(w.x, w.y);
    ((__half2*)E)[2 * i + 1] = __floats2half2_rn(w.z, w.w);
}

// row l2norm of fp32 rows (len kC) -> fp16
__global__ void l2norm_h(const float* __restrict__ src, __half* __restrict__ hi) {
    const float* p = src + (size_t)blockIdx.x * kC;
    float ss = 0.0f;
    #pragma unroll
    for (int i = threadIdx.x * 4; i < kC; i += 1024) {
        const float4 v = *(const float4*)(p + i);
        ss += v.x * v.x + v.y * v.y + v.z * v.z + v.w * v.w;
    }
    const float tot = block_reduce_sum(ss);
    const float inv = 1.0f / fmaxf(sqrtf(tot), 1e-12f);
    __half* ho = hi + (size_t)blockIdx.x * kC;
    #pragma unroll
    for (int i = threadIdx.x * 4; i < kC; i += 1024) {
        const float4 v = *(const float4*)(p + i);
        *(__half2*)(ho + i)     = __floats2half2_rn(v.x * inv, v.y * inv);
        *(__half2*)(ho + i + 2) = __floats2half2_rn(v.z * inv, v.w * inv);
    }
}

__global__ void transpose_v(const float* __restrict__ v, __half* __restrict__ vt) {
    __shared__ float t[32][33];
    const int b  = blockIdx.z;
    const int s0 = blockIdx.x * 32;
    const int d0 = blockIdx.y * 32;
    const int tx = threadIdx.x, ty = threadIdx.y;
    #pragma unroll
    for (int i = 0; i < 32; i += 8)
        t[ty + i][tx] = v[((size_t)b * kNS + s0 + ty + i) * kD + d0 + tx];
    __syncthreads();
    #pragma unroll
    for (int i = 0; i < 32; i += 8)
        vt[((size_t)b * kD + d0 + ty + i) * kNS + s0 + tx] = __float2half_rn(t[tx][ty + i]);
}

// reduce 32 per-block partials per row -> rowsum (deterministic fixed order)
__global__ void rowsum_reduce(const float* __restrict__ part, float* __restrict__ rs) {
    const int r = blockIdx.x * 256 + threadIdx.x;
    const float* p = part + (size_t)r * 32;
    float s = 0.0f;
    #pragma unroll
    for (int j = 0; j < 32; ++j) s += p[j];
    rs[r] = s;
}

// Normalize attn in place AND emit fp16 normalized weights for PV.
__global__ void attn_norm(float* __restrict__ P, const float* __restrict__ rs,
                          __half* __restrict__ Ph) {
    const size_t e = ((size_t)blockIdx.x * blockDim.x + threadIdx.x) * 4;
    const float inv = 1.0f / rs[e / kNS];
    float4 x = *(const float4*)(P + e);
    x.x *= inv; x.y *= inv; x.z *= inv; x.w *= inv;
    *(float4*)(P + e) = x;
    *(__half2*)(Ph + e)     = __floats2half2_rn(x.x, x.y);
    *(__half2*)(Ph + e + 2) = __floats2half2_rn(x.z, x.w);
}

// ---------------- launch ----------------
extern "C" void kernel_launch(void* const* d_in, const int* in_sizes, int n_in,
                              void* d_out, int out_size) {
    (void)in_sizes; (void)n_in; (void)out_size;
    const float* k     = (const float*)d_in[0];
    const float* v     = (const float*)d_in[1];
    const float* q     = (const float*)d_in[2];
    const float* idt   = (const float*)d_in[3];
    const float* mask  = (const float*)d_in[4];
    const float* W     = (const float*)d_in[5];
    const float* bias  = (const float*)d_in[6];
    const float* scale = (const float*)d_in[7];
    const float* attwt = (const float*)d_in[8];
    const float* orgwt = (const float*)d_in[9];

    float* out  = (float*)d_out;
    float* attn = out + (size_t)kB * kNQ * kD;

    __half *ah, *bh, *eh, *vt, *ph;
    float *qp, *kp, *rs, *part;
    cudaGetSymbolAddress((void**)&ah, g_ah);
    cudaGetSymbolAddress((void**)&bh, g_bh);
    cudaGetSymbolAddress((void**)&eh, g_eh);
    cudaGetSymbolAddress((void**)&vt, g_vt);
    cudaGetSymbolAddress((void**)&ph, g_ph);
    cudaGetSymbolAddress((void**)&qp, g_qp);
    cudaGetSymbolAddress((void**)&kp, g_kp);
    cudaGetSymbolAddress((void**)&rs, g_rowsum);
    cudaGetSymbolAddress((void**)&part, g_part);

    static bool attr_done = false;
    if (!attr_done) {
        cudaFuncSetAttribute(gemm_proj_k, cudaFuncAttributeMaxDynamicSharedMemorySize, SMEM_GM);
        cudaFuncSetAttribute(gemm_attn_k, cudaFuncAttributeMaxDynamicSharedMemorySize, SMEM_GM);
        cudaFuncSetAttribute(gemm_pv_k,   cudaFuncAttributeMaxDynamicSharedMemorySize, SMEM_GM);
        attr_done = true;
    }

    const size_t nq4 = (size_t)kMQ * kC / 4;
    to_half<<<(unsigned)((nq4 + 255) / 256), 256>>>(q, ah, nq4);
    to_half<<<(unsigned)((nq4 + 255) / 256), 256>>>(k, bh, nq4);
    const size_t nw4 = (size_t)kC * kC / 4;
    make_E<<<(unsigned)((nw4 + 255) / 256), 256>>>(W, eh);
    transpose_v<<<dim3(kNS / 32, kD / 32, kB), dim3(32, 8)>>>(v, vt);

    gemm_proj_k<<<dim3(kC / 128, kMQ / 128), 256, SMEM_GM>>>(ah, eh, q, bias, qp);
    gemm_proj_k<<<dim3(kC / 128, kMK / 128), 256, SMEM_GM>>>(bh, eh, k, bias, kp);

    l2norm_h<<<kMQ, 256>>>(qp, ah);
    l2norm_h<<<kMK, 256>>>(kp, bh);

    gemm_attn_k<<<dim3(kNS / 128, kNQ / 128, kB), 256, SMEM_GM>>>(ah, bh, mask, scale,
                                                                  attn, part);
    rowsum_reduce<<<kMQ / 256, 256>>>(part, rs);

    const size_t nvec4 = (size_t)kB * kNQ * kNS / 4;
    attn_norm<<<(unsigned)(nvec4 / 256), 256>>>(attn, rs, ph);

    gemm_pv_k<<<dim3(kD / 128, kMQ / 128), 256, SMEM_GM>>>(ph, vt, idt, attwt, orgwt, out);
}